// round 14
// baseline (speedup 1.0000x reference)
#include <cuda_runtime.h>
#include <math.h>
#include <stdint.h>

#define T_ 2048
#define H_ 2048
#define NH_ 16
#define NKV_ 4
#define DH_ 128
#define E_ 16
#define TOPK_ 2
#define I_ 1024
#define EPS_ 1e-6f

// ---------------- scratch ----------------
__device__ float g_cat[(size_t)T_ * 2 * H_];
__device__ float g_x[(size_t)T_ * H_];
__device__ float g_res[(size_t)T_ * H_];
__device__ float g_xn[(size_t)T_ * H_];
__device__ float g_qkv[(size_t)T_ * 3072];
__device__ float g_attn[(size_t)T_ * NH_ * DH_];
__device__ float g_s[(size_t)NH_ * T_ * T_];
__device__ float g_gbuf[(size_t)T_ * TOPK_ * I_];
__device__ float g_ubuf[(size_t)T_ * TOPK_ * I_];
__device__ float g_downbuf[(size_t)T_ * TOPK_ * H_];
__device__ int   g_top_idx[T_ * TOPK_];
__device__ float g_top_w[T_ * TOPK_];
__device__ int   g_counts[E_];
__device__ int   g_counts2[E_];
__device__ int   g_offs[E_ + 1];
__device__ int   g_tok_of_slot[T_ * TOPK_];
__device__ float g_gate_of_slot[T_ * TOPK_];
__device__ int   g_slot_of_tok[T_ * TOPK_];

// ---------------- helpers ----------------
__device__ __forceinline__ float block_reduce_sum(float v) {
    __shared__ float sb[33];
    int tid = threadIdx.x;
#pragma unroll
    for (int o = 16; o > 0; o >>= 1) v += __shfl_xor_sync(0xffffffffu, v, o);
    if ((tid & 31) == 0) sb[tid >> 5] = v;
    __syncthreads();
    if (tid == 0) {
        float s = 0.f;
        int nw = (blockDim.x + 31) >> 5;
        for (int i = 0; i < nw; i++) s += sb[i];
        sb[32] = s;
    }
    __syncthreads();
    return sb[32];
}
__device__ __forceinline__ float block_reduce_max(float v) {
    __shared__ float sb[33];
    int tid = threadIdx.x;
#pragma unroll
    for (int o = 16; o > 0; o >>= 1) v = fmaxf(v, __shfl_xor_sync(0xffffffffu, v, o));
    if ((tid & 31) == 0) sb[tid >> 5] = v;
    __syncthreads();
    if (tid == 0) {
        float s = -1e30f;
        int nw = (blockDim.x + 31) >> 5;
        for (int i = 0; i < nw; i++) s = fmaxf(s, sb[i]);
        sb[32] = s;
    }
    __syncthreads();
    return sb[32];
}

__device__ __forceinline__ void t32split(float x, uint32_t& h, uint32_t& l) {
    uint32_t hb;
    asm("cvt.rna.tf32.f32 %0, %1;" : "=r"(hb) : "f"(x));
    float hf = __uint_as_float(hb);
    asm("cvt.rna.tf32.f32 %0, %1;" : "=r"(l) : "f"(x - hf));
    h = hb;
}
__device__ __forceinline__ void store_split(float2* p, float x) {
    uint32_t h, l;
    t32split(x, h, l);
    *p = make_float2(__uint_as_float(h), __uint_as_float(l));
}
__device__ __forceinline__ void mma_tf32(float* d, const uint32_t* a, const uint32_t* b) {
    asm volatile("mma.sync.aligned.m16n8k8.row.col.f32.tf32.tf32.f32 "
                 "{%0,%1,%2,%3}, {%4,%5,%6,%7}, {%8,%9}, {%0,%1,%2,%3};"
                 : "+f"(d[0]), "+f"(d[1]), "+f"(d[2]), "+f"(d[3])
                 : "r"(a[0]), "r"(a[1]), "r"(a[2]), "r"(a[3]), "r"(b[0]), "r"(b[1]));
}

#define TP2 132   // pitch in float2; row stride 264 words == 8 mod 32 -> conflict-free
#define DSM_BYTES (4 * 16 * TP2 * 8)   // As[2] + Bs[2], float2 elements (~66KB)

// ---------------- 3xTF32 tensor GEMM skeleton: 128x128 tile, 8 warps (4m x 2n) ----------------
// smem holds pre-split (hi,lo) pairs; compute loads float2 and feeds MMA directly.
#define T32_DECL()                                                                   \
    extern __shared__ float2 dynsm_[];                                               \
    float2* As_ = dynsm_;                                                            \
    float2* Bs_ = dynsm_ + 2 * 16 * TP2;                                             \
    int tid = threadIdx.x, lane = tid & 31, wid = tid >> 5;                          \
    int m0 = (wid & 3) * 32, n0 = (wid >> 2) * 64;                                   \
    int fr = lane >> 2, kc = lane & 3;                                               \
    int am = tid & 127, ak0 = (tid >> 7) * 8;                                        \
    float acc[2][8][4];                                                              \
    _Pragma("unroll") for (int i_ = 0; i_ < 2; i_++)                                 \
        _Pragma("unroll") for (int j_ = 0; j_ < 8; j_++)                             \
            _Pragma("unroll") for (int c_ = 0; c_ < 4; c_++) acc[i_][j_][c_] = 0.f;  \
    float4 ra0, ra1, rb0, rb1;                                                       \
    const float4 Z4 = make_float4(0.f, 0.f, 0.f, 0.f);                               \
    (void)Z4;

#define T32_STORE_A_TR(BUF)                                                          \
    do {                                                                             \
        float2* p_ = As_ + (BUF) * 16 * TP2 + ak0 * TP2 + am;                        \
        store_split(p_ + 0 * TP2, ra0.x); store_split(p_ + 1 * TP2, ra0.y);          \
        store_split(p_ + 2 * TP2, ra0.z); store_split(p_ + 3 * TP2, ra0.w);          \
        store_split(p_ + 4 * TP2, ra1.x); store_split(p_ + 5 * TP2, ra1.y);          \
        store_split(p_ + 6 * TP2, ra1.z); store_split(p_ + 7 * TP2, ra1.w);          \
    } while (0)

#define T32_STORE_B_TR(BUF)                                                          \
    do {                                                                             \
        float2* p_ = Bs_ + (BUF) * 16 * TP2 + ak0 * TP2 + am;                        \
        store_split(p_ + 0 * TP2, rb0.x); store_split(p_ + 1 * TP2, rb0.y);          \
        store_split(p_ + 2 * TP2, rb0.z); store_split(p_ + 3 * TP2, rb0.w);          \
        store_split(p_ + 4 * TP2, rb1.x); store_split(p_ + 5 * TP2, rb1.y);          \
        store_split(p_ + 6 * TP2, rb1.z); store_split(p_ + 7 * TP2, rb1.w);          \
    } while (0)

#define T32_STORE_B_ROW(BUF, BR0, BC4)                                               \
    do {                                                                             \
        float2* p0_ = Bs_ + (BUF) * 16 * TP2 + (BR0) * TP2 + (BC4) * 4;              \
        store_split(p0_ + 0, rb0.x); store_split(p0_ + 1, rb0.y);                    \
        store_split(p0_ + 2, rb0.z); store_split(p0_ + 3, rb0.w);                    \
        float2* p1_ = p0_ + 8 * TP2;                                                 \
        store_split(p1_ + 0, rb1.x); store_split(p1_ + 1, rb1.y);                    \
        store_split(p1_ + 2, rb1.z); store_split(p1_ + 3, rb1.w);                    \
    } while (0)

#define T32_COMPUTE(CUR)                                                             \
    _Pragma("unroll")                                                                \
    for (int s = 0; s < 2; s++) {                                                    \
        const float2* Ab  = As_ + (CUR) * 16 * TP2 + (s * 8 + kc) * TP2;             \
        const float2* Ab4 = Ab + 4 * TP2;                                            \
        const float2* Bb  = Bs_ + (CUR) * 16 * TP2 + (s * 8 + kc) * TP2;             \
        const float2* Bb4 = Bb + 4 * TP2;                                            \
        uint32_t ah[2][4], al[2][4], bh[8][2], bl[8][2];                             \
        _Pragma("unroll")                                                            \
        for (int mt = 0; mt < 2; mt++) {                                             \
            int mm = m0 + mt * 16 + fr;                                              \
            float2 t_;                                                               \
            t_ = Ab[mm];      ah[mt][0] = __float_as_uint(t_.x); al[mt][0] = __float_as_uint(t_.y); \
            t_ = Ab[mm + 8];  ah[mt][1] = __float_as_uint(t_.x); al[mt][1] = __float_as_uint(t_.y); \
            t_ = Ab4[mm];     ah[mt][2] = __float_as_uint(t_.x); al[mt][2] = __float_as_uint(t_.y); \
            t_ = Ab4[mm + 8]; ah[mt][3] = __float_as_uint(t_.x); al[mt][3] = __float_as_uint(t_.y); \
        }                                                                            \
        _Pragma("unroll")                                                            \
        for (int nt = 0; nt < 8; nt++) {                                             \
            int nn = n0 + nt * 8 + fr;                                               \
            float2 t_;                                                               \
            t_ = Bb[nn];  bh[nt][0] = __float_as_uint(t_.x); bl[nt][0] = __float_as_uint(t_.y); \
            t_ = Bb4[nn]; bh[nt][1] = __float_as_uint(t_.x); bl[nt][1] = __float_as_uint(t_.y); \
        }                                                                            \
        _Pragma("unroll")                                                            \
        for (int mt = 0; mt < 2; mt++)                                               \
            _Pragma("unroll")                                                        \
            for (int nt = 0; nt < 8; nt++) {                                         \
                mma_tf32(acc[mt][nt], ah[mt], bh[nt]);                               \
                mma_tf32(acc[mt][nt], ah[mt], bl[nt]);                               \
                mma_tf32(acc[mt][nt], al[mt], bh[nt]);                               \
            }                                                                        \
    }

// ---------------- generic weight GEMM (A row-major gather, B row-major) ----------------
__global__ __launch_bounds__(256, 2)
void gemm_t32(const float* __restrict__ A, const float* __restrict__ B,
              float* __restrict__ C,
              int M, int Kd, int lda, int ldb, int ldc,
              const int* __restrict__ rowmap,
              const float* __restrict__ addsrc, float* __restrict__ Cdup,
              const int* __restrict__ segoff, long long strideB,
              const float* __restrict__ rowscale) {
    int row0 = 0, rowEnd = M;
    const float* Bp = B;
    if (segoff) {
        int e = blockIdx.z;
        row0 = segoff[e];
        rowEnd = segoff[e + 1];
        Bp = B + (long long)e * strideB;
    }
    int rbase = row0 + blockIdx.y * 128;
    if (rbase >= rowEnd) return;
    int cbase = blockIdx.x * 128;

    T32_DECL();
    const float* Arow = nullptr;
    if (rbase + am < rowEnd) {
        int m = rowmap ? rowmap[rbase + am] : rbase + am;
        Arow = A + (long long)m * lda;
    }
    const float* Brow_ = Bp + cbase;
    int br0 = tid >> 5, bc4 = tid & 31;

#define LOADG(K0)                                                                    \
    do {                                                                             \
        if (Arow) {                                                                  \
            ra0 = *(const float4*)(Arow + (K0) + ak0);                               \
            ra1 = *(const float4*)(Arow + (K0) + ak0 + 4);                           \
        } else { ra0 = Z4; ra1 = Z4; }                                               \
        rb0 = *(const float4*)(Brow_ + (long long)((K0) + br0) * ldb + bc4 * 4);     \
        rb1 = *(const float4*)(Brow_ + (long long)((K0) + br0 + 8) * ldb + bc4 * 4); \
    } while (0)

    int nk = Kd >> 4;
    LOADG(0);
    T32_STORE_A_TR(0);
    T32_STORE_B_ROW(0, br0, bc4);
    __syncthreads();
    for (int kt = 0; kt < nk; kt++) {
        int cur = kt & 1;
        if (kt + 1 < nk) LOADG((kt + 1) * 16);
        T32_COMPUTE(cur);
        if (kt + 1 < nk) {
            T32_STORE_A_TR(cur ^ 1);
            T32_STORE_B_ROW(cur ^ 1, br0, bc4);
            __syncthreads();
        }
    }
#undef LOADG

#pragma unroll
    for (int mt = 0; mt < 2; mt++)
#pragma unroll
        for (int half = 0; half < 2; half++) {
            int row = rbase + m0 + mt * 16 + fr + half * 8;
            if (row >= rowEnd) continue;
            float sc = rowscale ? rowscale[row] : 1.f;
            long long base = (long long)row * ldc + cbase + n0 + 2 * kc;
#pragma unroll
            for (int nt = 0; nt < 8; nt++) {
                long long o = base + nt * 8;
                float2 v = make_float2(acc[mt][nt][half * 2 + 0] * sc,
                                       acc[mt][nt][half * 2 + 1] * sc);
                if (addsrc) {
                    float2 s = *(const float2*)(addsrc + o);
                    v.x += s.x; v.y += s.y;
                }
                *(float2*)(C + o) = v;
                if (Cdup) *(float2*)(Cdup + o) = v;
            }
        }
}

// fused QKV variant -> g_qkv[T][3072]
__global__ __launch_bounds__(256, 2)
void gemm_t32_qkv(const float* __restrict__ A,
                  const float* __restrict__ wq, const float* __restrict__ wk,
                  const float* __restrict__ wv) {
    int x = blockIdx.x;
    const float* Bsel;
    int ldb, bcol;
    if (x < 16)      { Bsel = wq; ldb = 2048; bcol = x * 128; }
    else if (x < 20) { Bsel = wk; ldb = 512;  bcol = (x - 16) * 128; }
    else             { Bsel = wv; ldb = 512;  bcol = (x - 20) * 128; }
    int ccol = x * 128;
    int rbase = blockIdx.y * 128;

    T32_DECL();
    const float* Arow = A + (long long)(rbase + am) * H_;
    const float* Brow_ = Bsel + bcol;
    int br0 = tid >> 5, bc4 = tid & 31;

#define LOADG(K0)                                                                    \
    do {                                                                             \
        ra0 = *(const float4*)(Arow + (K0) + ak0);                                   \
        ra1 = *(const float4*)(Arow + (K0) + ak0 + 4);                               \
        rb0 = *(const float4*)(Brow_ + (long long)((K0) + br0) * ldb + bc4 * 4);     \
        rb1 = *(const float4*)(Brow_ + (long long)((K0) + br0 + 8) * ldb + bc4 * 4); \
    } while (0)

    int nk = H_ >> 4;
    LOADG(0);
    T32_STORE_A_TR(0);
    T32_STORE_B_ROW(0, br0, bc4);
    __syncthreads();
    for (int kt = 0; kt < nk; kt++) {
        int cur = kt & 1;
        if (kt + 1 < nk) LOADG((kt + 1) * 16);
        T32_COMPUTE(cur);
        if (kt + 1 < nk) {
            T32_STORE_A_TR(cur ^ 1);
            T32_STORE_B_ROW(cur ^ 1, br0, bc4);
            __syncthreads();
        }
    }
#undef LOADG

#pragma unroll
    for (int mt = 0; mt < 2; mt++)
#pragma unroll
        for (int half = 0; half < 2; half++) {
            int row = rbase + m0 + mt * 16 + fr + half * 8;
            long long base = (long long)row * 3072 + ccol + n0 + 2 * kc;
#pragma unroll
            for (int nt = 0; nt < 8; nt++)
                *(float2*)(g_qkv + base + nt * 8) =
                    make_float2(acc[mt][nt][half * 2 + 0], acc[mt][nt][half * 2 + 1]);
        }
}

// ---------------- attention pass A (3xTF32): S = scale*Q@K^T, causal tiles ----------------
__global__ __launch_bounds__(256, 2)
void gemm_t32_qk() {
    int ktile = blockIdx.x, qtile = blockIdx.y, h = blockIdx.z;
    if (ktile > qtile) return;
    int qbase = qtile * 128, kbase = ktile * 128, kvh = h >> 2;

    T32_DECL();
    const float* Arow = g_qkv + (size_t)(qbase + am) * 3072 + h * DH_;
    const float* Brow = g_qkv + (size_t)(kbase + am) * 3072 + 2048 + kvh * DH_;

#define LOADG(K0)                                                                    \
    do {                                                                             \
        ra0 = *(const float4*)(Arow + (K0) + ak0);                                   \
        ra1 = *(const float4*)(Arow + (K0) + ak0 + 4);                               \
        rb0 = *(const float4*)(Brow + (K0) + ak0);                                   \
        rb1 = *(const float4*)(Brow + (K0) + ak0 + 4);                               \
    } while (0)

    const int nk = DH_ >> 4;   // 8
    LOADG(0);
    T32_STORE_A_TR(0);
    T32_STORE_B_TR(0);
    __syncthreads();
    for (int kt = 0; kt < nk; kt++) {
        int cur = kt & 1;
        if (kt + 1 < nk) LOADG((kt + 1) * 16);
        T32_COMPUTE(cur);
        if (kt + 1 < nk) {
            T32_STORE_A_TR(cur ^ 1);
            T32_STORE_B_TR(cur ^ 1);
            __syncthreads();
        }
    }
#undef LOADG

    const float scale = 0.08838834764831845f;
#pragma unroll
    for (int mt = 0; mt < 2; mt++)
#pragma unroll
        for (int half = 0; half < 2; half++) {
            int q = qbase + m0 + mt * 16 + fr + half * 8;
            float* srow = g_s + ((size_t)h * T_ + q) * T_ + kbase + n0 + 2 * kc;
            int k0 = kbase + n0 + 2 * kc;
#pragma unroll
            for (int nt = 0; nt < 8; nt++) {
                float v0 = (k0 + nt * 8 + 0 <= q) ? acc[mt][nt][half * 2 + 0] * scale : -1e30f;
                float v1 = (k0 + nt * 8 + 1 <= q) ? acc[mt][nt][half * 2 + 1] * scale : -1e30f;
                *(float2*)(srow + nt * 8) = make_float2(v0, v1);
            }
        }
}

// ---------------- attention pass B: row softmax ----------------
__global__ __launch_bounds__(256)
void softmax_rows() {
    int q = blockIdx.x, h = blockIdx.y;
    float* row = g_s + ((size_t)h * T_ + q) * T_;
    int L = q + 1, pad_end = ((q >> 7) + 1) << 7, tid = threadIdx.x;
    float v[8];
    int nchunk = (L + 255) >> 8;
    float mx = -1e30f;
#pragma unroll 4
    for (int c = 0; c < nchunk; c++) {
        int i = c * 256 + tid;
        v[c] = (i < L) ? row[i] : -1e30f;
        mx = fmaxf(mx, v[c]);
    }
    mx = block_reduce_max(mx);
    float s = 0.f;
#pragma unroll 4
    for (int c = 0; c < nchunk; c++) { v[c] = __expf(v[c] - mx); s += v[c]; }
    float tot = block_reduce_sum(s);
    float inv = 1.f / tot;
#pragma unroll 4
    for (int c = 0; c < nchunk; c++) {
        int i = c * 256 + tid;
        if (i < L) row[i] = v[c] * inv;
    }
    for (int i = L + tid; i < pad_end; i += 256) row[i] = 0.f;
}

// ---------------- attention pass C (3xTF32): O = P @ V ----------------
__global__ __launch_bounds__(256, 2)
void gemm_t32_pv() {
    int qt = (int)gridDim.x - 1 - (int)blockIdx.x;   // longest first
    int h = blockIdx.y;
    int rbase = qt * 128, kvh = h >> 2;

    T32_DECL();
    const float* Arow = g_s + (size_t)h * T_ * T_ + (size_t)(rbase + am) * T_;
    const float* Bp = g_qkv + 2560 + kvh * DH_;     // V, row stride 3072
    int br0 = tid >> 5, bc4 = tid & 31;

#define LOADG(K0)                                                                    \
    do {                                                                             \
        ra0 = *(const float4*)(Arow + (K0) + ak0);                                   \
        ra1 = *(const float4*)(Arow + (K0) + ak0 + 4);                               \
        rb0 = *(const float4*)(Bp + (size_t)((K0) + br0) * 3072 + bc4 * 4);          \
        rb1 = *(const float4*)(Bp + (size_t)((K0) + br0 + 8) * 3072 + bc4 * 4);      \
    } while (0)

    int nk = (qt + 1) * 8;
    LOADG(0);
    T32_STORE_A_TR(0);
    T32_STORE_B_ROW(0, br0, bc4);
    __syncthreads();
    for (int kt = 0; kt < nk; kt++) {
        int cur = kt & 1;
        if (kt + 1 < nk) LOADG((kt + 1) * 16);
        T32_COMPUTE(cur);
        if (kt + 1 < nk) {
            T32_STORE_A_TR(cur ^ 1);
            T32_STORE_B_ROW(cur ^ 1, br0, bc4);
            __syncthreads();
        }
    }
#undef LOADG

#pragma unroll
    for (int mt = 0; mt < 2; mt++)
#pragma unroll
        for (int half = 0; half < 2; half++) {
            int q = rbase + m0 + mt * 16 + fr + half * 8;
            float* dst = g_attn + (size_t)q * (NH_ * DH_) + h * DH_ + n0 + 2 * kc;
#pragma unroll
            for (int nt = 0; nt < 8; nt++)
                *(float2*)(dst + nt * 8) =
                    make_float2(acc[mt][nt][half * 2 + 0], acc[mt][nt][half * 2 + 1]);
        }
}

// ---------------- elementwise ----------------
__global__ void embcat_kernel(const int* __restrict__ ids,
                              const float* __restrict__ emb_w,
                              const float* __restrict__ hid,
                              const float* __restrict__ we,
                              const float* __restrict__ wh) {
    int t = blockIdx.x;
    const float* er = emb_w + (size_t)ids[t] * H_;
    const float* hr = hid + (size_t)t * H_;
    float ss = 0.f;
    for (int h = threadIdx.x; h < H_; h += blockDim.x) { float v = er[h]; ss += v * v; }
    float rs = rsqrtf(block_reduce_sum(ss) / H_ + EPS_);
    for (int h = threadIdx.x; h < H_; h += blockDim.x)
        g_cat[(size_t)t * 2 * H_ + h] = er[h] * rs * (1.f + we[h]);
    ss = 0.f;
    for (int h = threadIdx.x; h < H_; h += blockDim.x) { float v = hr[h]; ss += v * v; }
    rs = rsqrtf(block_reduce_sum(ss) / H_ + EPS_);
    for (int h = threadIdx.x; h < H_; h += blockDim.x)
        g_cat[(size_t)t * 2 * H_ + H_ + h] = hr[h] * rs * (1.f + wh[h]);
}

__global__ void rmsnorm_kernel(const float* __restrict__ in,
                               const float* __restrict__ w,
                               float* __restrict__ out) {
    int t = blockIdx.x;
    const float* r = in + (size_t)t * H_;
    float ss = 0.f;
    for (int h = threadIdx.x; h < H_; h += blockDim.x) { float v = r[h]; ss += v * v; }
    float rs = rsqrtf(block_reduce_sum(ss) / H_ + EPS_);
    for (int h = threadIdx.x; h < H_; h += blockDim.x)
        out[(size_t)t * H_ + h] = r[h] * rs * (1.f + w[h]);
}

__global__ void qkrope_kernel(int coloff, int nheads,
                              const float* __restrict__ nw,
                              const int* __restrict__ positions) {
    int t = blockIdx.x, h = blockIdx.y;
    float* v = g_qkv + (size_t)t * 3072 + coloff + h * DH_;
    int d = threadIdx.x;
    float val = v[d];
    float ss = val * val;
#pragma unroll
    for (int o = 16; o > 0; o >>= 1) ss += __shfl_xor_sync(0xffffffffu, ss, o);
    __shared__ float ws[4];
    if ((d & 31) == 0) ws[d >> 5] = ss;
    __syncthreads();
    float rs = rsqrtf((ws[0] + ws[1] + ws[2] + ws[3]) / DH_ + EPS_);
    float n = val * rs * (1.f + nw[d]);
    __shared__ float nv[DH_];
    nv[d] = n;
    __syncthreads();
    int pos = positions[t];
    int i = d & 63;
    float inv = expf(-((float)i / 64.f) * 13.815510557964274f);
    float ang = (float)pos * inv;
    float c = cosf(ang), s = sinf(ang);
    v[d] = (d < 64) ? nv[d] * c - nv[d + 64] * s : nv[d] * c + nv[d - 64] * s;
}

__global__ void zero_counts_kernel() { if (threadIdx.x < E_) g_counts[threadIdx.x] = 0; }

__global__ void router_kernel(const float* __restrict__ rw) {
    int t = blockIdx.x;
    __shared__ float part[256];
    __shared__ float logits[E_];
    int tid = threadIdx.x, e = tid >> 4, c = tid & 15;
    float s = 0.f;
    const float* xr = g_xn + (size_t)t * H_;
    for (int h = c * 128; h < (c + 1) * 128; h++) s += xr[h] * rw[(size_t)h * E_ + e];
    part[tid] = s;
    __syncthreads();
    if (c == 0) {
        float tot = 0.f;
        for (int i = 0; i < 16; i++) tot += part[e * 16 + i];
        logits[e] = tot;
    }
    __syncthreads();
    if (tid == 0) {
        float mx = -1e30f;
        for (int i = 0; i < E_; i++) mx = fmaxf(mx, logits[i]);
        float p[E_];
        for (int i = 0; i < E_; i++) p[i] = expf(logits[i] - mx);
        int i0 = 0; float v0 = p[0];
        for (int i = 1; i < E_; i++) if (p[i] > v0) { v0 = p[i]; i0 = i; }
        int i1 = -1; float v1 = -1.f;
        for (int i = 0; i < E_; i++) if (i != i0 && p[i] > v1) { v1 = p[i]; i1 = i; }
        float denom = v0 + v1;
        g_top_idx[t * 2 + 0] = i0; g_top_idx[t * 2 + 1] = i1;
        g_top_w[t * 2 + 0] = v0 / denom; g_top_w[t * 2 + 1] = v1 / denom;
        atomicAdd(&g_counts[i0], 1);
        atomicAdd(&g_counts[i1], 1);
    }
}

__global__ void offsets_kernel() {
    if (threadIdx.x == 0) {
        int acc = 0;
        for (int e = 0; e < E_; e++) { g_offs[e] = acc; acc += g_counts[e]; }
        g_offs[E_] = acc;
    }
    if (threadIdx.x < E_) g_counts2[threadIdx.x] = 0;
}

__global__ void scatter_kernel() {
    int t = blockIdx.x * blockDim.x + threadIdx.x;
    if (t >= T_) return;
    for (int k = 0; k < TOPK_; k++) {
        int e = g_top_idx[t * 2 + k];
        int pos = atomicAdd(&g_counts2[e], 1);
        int slot = g_offs[e] + pos;
        g_tok_of_slot[slot] = t;
        g_gate_of_slot[slot] = g_top_w[t * 2 + k];
        g_slot_of_tok[t * 2 + k] = slot;
    }
}

__global__ void silu_mul_kernel() {
    size_t i = (size_t)blockIdx.x * blockDim.x + threadIdx.x;
    if (i >= (size_t)T_ * TOPK_ * I_) return;
    float x = g_gbuf[i];
    g_gbuf[i] = (x / (1.f + expf(-x))) * g_ubuf[i];
}

__global__ void final_kernel(const float* __restrict__ fw, float* __restrict__ out) {
    int t = blockIdx.x;
    __shared__ float buf[H_];
    int s0 = g_slot_of_tok[t * 2 + 0], s1 = g_slot_of_tok[t * 2 + 1];
    float ss = 0.f;
    for (int h = threadIdx.x; h < H_; h += blockDim.x) {
        float v = g_x[(size_t)t * H_ + h] + g_downbuf[(size_t)s0 * H_ + h] +
                  g_downbuf[(size_t)s1 * H_ + h];
        buf[h] = v;
        ss += v * v;
    }
    float rs = rsqrtf(block_reduce_sum(ss) / H_ + EPS_);
    for (int h = threadIdx.x; h < H_; h += blockDim.x)
        out[(size_t)t * H_ + h] = buf[h] * rs * (1.f + fw[h]);
}

// ---------------- launch ----------------
extern "C" void kernel_launch(void* const* d_in, const int* in_sizes, int n_in,
                              void* d_out, int out_size) {
    const int* input_ids      = (const int*)d_in[0];
    const int* positions      = (const int*)d_in[1];
    const float* hidden       = (const float*)d_in[2];
    const float* embed_w      = (const float*)d_in[4];
    const float* fc_w         = (const float*)d_in[5];
    const float* pre_fc_emb_w = (const float*)d_in[6];
    const float* pre_fc_hid_w = (const float*)d_in[7];
    const float* in_ln_w      = (const float*)d_in[8];
    const float* post_ln_w    = (const float*)d_in[9];
    const float* final_norm_w = (const float*)d_in[10];
    const float* wq           = (const float*)d_in[11];
    const float* wk           = (const float*)d_in[12];
    const float* wv           = (const float*)d_in[13];
    const float* wo           = (const float*)d_in[14];
    const float* q_norm_w     = (const float*)d_in[15];
    const float* k_norm_w     = (const float*)d_in[16];
    const float* router_w     = (const float*)d_in[17];
    const float* w_gate       = (const float*)d_in[18];
    const float* w_up         = (const float*)d_in[19];
    const float* w_down       = (const float*)d_in[20];
    float* out = (float*)d_out;

    float *p_cat, *p_x, *p_res, *p_xn, *p_attn, *p_g, *p_u, *p_down, *p_gate;
    int *p_tok, *p_offs;
    cudaGetSymbolAddress((void**)&p_cat, g_cat);
    cudaGetSymbolAddress((void**)&p_x, g_x);
    cudaGetSymbolAddress((void**)&p_res, g_res);
    cudaGetSymbolAddress((void**)&p_xn, g_xn);
    cudaGetSymbolAddress((void**)&p_attn, g_attn);
    cudaGetSymbolAddress((void**)&p_g, g_gbuf);
    cudaGetSymbolAddress((void**)&p_u, g_ubuf);
    cudaGetSymbolAddress((void**)&p_down, g_downbuf);
    cudaGetSymbolAddress((void**)&p_gate, g_gate_of_slot);
    cudaGetSymbolAddress((void**)&p_tok, g_tok_of_slot);
    cudaGetSymbolAddress((void**)&p_offs, g_offs);

    cudaFuncSetAttribute(gemm_t32, cudaFuncAttributeMaxDynamicSharedMemorySize, DSM_BYTES);
    cudaFuncSetAttribute(gemm_t32_qkv, cudaFuncAttributeMaxDynamicSharedMemorySize, DSM_BYTES);
    cudaFuncSetAttribute(gemm_t32_qk, cudaFuncAttributeMaxDynamicSharedMemorySize, DSM_BYTES);
    cudaFuncSetAttribute(gemm_t32_pv, cudaFuncAttributeMaxDynamicSharedMemorySize, DSM_BYTES);

    // 1. embed + rms -> concat
    embcat_kernel<<<T_, 256>>>(input_ids, embed_w, hidden, pre_fc_emb_w, pre_fc_hid_w);

    // 2. fc (3xTF32): x = cat @ fc_w ; residual = x
    gemm_t32<<<dim3(H_ / 128, T_ / 128), 256, DSM_BYTES>>>(
        p_cat, fc_w, p_x, T_, 2 * H_, 2 * H_, H_, H_,
        nullptr, nullptr, p_res, nullptr, 0, nullptr);

    // 3. in_ln
    rmsnorm_kernel<<<T_, 256>>>(p_x, in_ln_w, p_xn);

    // 4. fused qkv (3xTF32)
    gemm_t32_qkv<<<dim3(24, T_ / 128), 256, DSM_BYTES>>>(p_xn, wq, wk, wv);

    // 5. q/k norm + rope
    qkrope_kernel<<<dim3(T_, NH_), DH_>>>(0, NH_, q_norm_w, positions);
    qkrope_kernel<<<dim3(T_, NKV_), DH_>>>(2048, NKV_, k_norm_w, positions);

    // 6. attention: QK^T (3xTF32) -> softmax (fp32) -> PV (3xTF32)
    gemm_t32_qk<<<dim3(T_ / 128, T_ / 128, NH_), 256, DSM_BYTES>>>();
    softmax_rows<<<dim3(T_, NH_), 256>>>();
    gemm_t32_pv<<<dim3(T_ / 128, NH_), 256, DSM_BYTES>>>();

    // 7. wo + residual (3xTF32)
    gemm_t32<<<dim3(H_ / 128, T_ / 128), 256, DSM_BYTES>>>(
        p_attn, wo, p_x, T_, NH_ * DH_, NH_ * DH_, H_, H_,
        nullptr, p_res, nullptr, nullptr, 0, nullptr);

    // 8. post_ln
    rmsnorm_kernel<<<T_, 256>>>(p_x, post_ln_w, p_xn);

    // 9. router + bucketing
    zero_counts_kernel<<<1, 32>>>();
    router_kernel<<<T_, 256>>>(router_w);
    offsets_kernel<<<1, 32>>>();
    scatter_kernel<<<(T_ + 255) / 256, 256>>>();

    // 10. MoE grouped GEMMs (3xTF32)
    gemm_t32<<<dim3(I_ / 128, T_ / 128, E_), 256, DSM_BYTES>>>(
        p_xn, w_gate, p_g, 0, H_, H_, I_, I_,
        p_tok, nullptr, nullptr, p_offs, (long long)H_ * I_, nullptr);
    gemm_t32<<<dim3(I_ / 128, T_ / 128, E_), 256, DSM_BYTES>>>(
        p_xn, w_up, p_u, 0, H_, H_, I_, I_,
        p_tok, nullptr, nullptr, p_offs, (long long)H_ * I_, nullptr);
    silu_mul_kernel<<<((size_t)T_ * TOPK_ * I_ + 255) / 256, 256>>>();
    gemm_t32<<<dim3(H_ / 128, T_ / 128, E_), 256, DSM_BYTES>>>(
        p_g, w_down, p_down, 0, I_, I_, H_, H_,
        nullptr, nullptr, nullptr, p_offs, (long long)I_ * H_, p_gate);

    // 11. combine + final rms
    final_kernel<<<T_, 256>>>(final_norm_w, out);
}

// round 15
// speedup vs baseline: 1.7486x; 1.7486x over previous
#include <cuda_runtime.h>
#include <cuda_bf16.h>
#include <math.h>
#include <stdint.h>

#define T_ 2048
#define H_ 2048
#define NH_ 16
#define NKV_ 4
#define DH_ 128
#define E_ 16
#define TOPK_ 2
#define I_ 1024
#define EPS_ 1e-6f

// ---------------- fp32 scratch ----------------
__device__ float g_x[(size_t)T_ * H_];
__device__ float g_res[(size_t)T_ * H_];
__device__ float g_xn[(size_t)T_ * H_];
__device__ float g_qkv[(size_t)T_ * 3072];          // q,k fp32 (pre-rope); v unused
__device__ float g_s[(size_t)NH_ * T_ * T_];        // scores fp32 -> packed probs in place
__device__ float g_gbuf[(size_t)T_ * TOPK_ * I_];
__device__ float g_ubuf[(size_t)T_ * TOPK_ * I_];
__device__ float g_downbuf[(size_t)T_ * TOPK_ * H_];
__device__ int   g_top_idx[T_ * TOPK_];
__device__ float g_top_w[T_ * TOPK_];
__device__ int   g_counts[E_];
__device__ int   g_counts2[E_];
__device__ int   g_offs[E_ + 1];
__device__ int   g_tok_of_slot[T_ * TOPK_];
__device__ float g_gate_of_slot[T_ * TOPK_];
__device__ int   g_slot_of_tok[T_ * TOPK_];

// ---------------- packed (hi,lo) bf16 planes ----------------
#define WOFF_FC 0LL
#define WOFF_Q  8388608LL
#define WOFF_K  12582912LL
#define WOFF_V  13631488LL
#define WOFF_O  14680064LL
#define WOFF_G  18874368LL
#define WOFF_U  52428800LL
#define WOFF_D  85983232LL
#define WTOT    119537664LL
__device__ uint32_t g_wp[WTOT];                     // packed weights
__device__ uint32_t g_catp[(size_t)T_ * 2 * H_];
__device__ uint32_t g_xnp[(size_t)T_ * H_];
__device__ uint32_t g_qp[(size_t)T_ * NH_ * DH_];
__device__ uint32_t g_kp[(size_t)T_ * NKV_ * DH_];
__device__ uint32_t g_vp[(size_t)T_ * NKV_ * DH_];
__device__ uint32_t g_attnp[(size_t)T_ * H_];
__device__ uint32_t g_actp[(size_t)T_ * TOPK_ * I_];

// ---------------- helpers ----------------
__device__ __forceinline__ float block_reduce_sum(float v) {
    __shared__ float sb[33];
    int tid = threadIdx.x;
#pragma unroll
    for (int o = 16; o > 0; o >>= 1) v += __shfl_xor_sync(0xffffffffu, v, o);
    if ((tid & 31) == 0) sb[tid >> 5] = v;
    __syncthreads();
    if (tid == 0) {
        float s = 0.f;
        int nw = (blockDim.x + 31) >> 5;
        for (int i = 0; i < nw; i++) s += sb[i];
        sb[32] = s;
    }
    __syncthreads();
    return sb[32];
}
__device__ __forceinline__ float block_reduce_max(float v) {
    __shared__ float sb[33];
    int tid = threadIdx.x;
#pragma unroll
    for (int o = 16; o > 0; o >>= 1) v = fmaxf(v, __shfl_xor_sync(0xffffffffu, v, o));
    if ((tid & 31) == 0) sb[tid >> 5] = v;
    __syncthreads();
    if (tid == 0) {
        float s = -1e30f;
        int nw = (blockDim.x + 31) >> 5;
        for (int i = 0; i < nw; i++) s = fmaxf(s, sb[i]);
        sb[32] = s;
    }
    __syncthreads();
    return sb[32];
}

__device__ __forceinline__ uint32_t packsplit(float x) {
    __nv_bfloat16 h = __float2bfloat16_rn(x);
    float hf = __bfloat162float(h);
    __nv_bfloat16 l = __float2bfloat16_rn(x - hf);
    return (uint32_t)__bfloat16_as_ushort(h) |
           ((uint32_t)__bfloat16_as_ushort(l) << 16);
}
__device__ __forceinline__ void mma_bf16(float* d, const uint32_t* a, const uint32_t* b) {
    asm volatile("mma.sync.aligned.m16n8k16.row.col.f32.bf16.bf16.f32 "
                 "{%0,%1,%2,%3}, {%4,%5,%6,%7}, {%8,%9}, {%0,%1,%2,%3};"
                 : "+f"(d[0]), "+f"(d[1]), "+f"(d[2]), "+f"(d[3])
                 : "r"(a[0]), "r"(a[1]), "r"(a[2]), "r"(a[3]), "r"(b[0]), "r"(b[1]));
}

#define TPW 136  // word pitch; 136 % 32 = 8 -> conflict-free with k-row permutation

// k-row permutation: logical k -> physical row (k&1)*8 + (k>>1)
// thread (fr,kc) needs logical {2kc,2kc+1,2kc+8,2kc+9} = physical {kc, 8+kc, 4+kc, 12+kc}
#define B16_DECL()                                                                   \
    __shared__ uint32_t As[2][16 * TPW];                                             \
    __shared__ uint32_t Bs[2][16 * TPW];                                             \
    int tid = threadIdx.x, lane = tid & 31, wid = tid >> 5;                          \
    int m0 = (wid & 3) * 32, n0 = (wid >> 2) * 64;                                   \
    int fr = lane >> 2, kc = lane & 3;                                               \
    int am = tid & 127, ak0 = (tid >> 7) * 8;                                        \
    float acc[2][8][4];                                                              \
    _Pragma("unroll") for (int i_ = 0; i_ < 2; i_++)                                 \
        _Pragma("unroll") for (int j_ = 0; j_ < 8; j_++)                             \
            _Pragma("unroll") for (int c_ = 0; c_ < 4; c_++) acc[i_][j_][c_] = 0.f;  \
    uint4 ra0, ra1, rb0, rb1;                                                        \
    const uint4 Z4 = make_uint4(0, 0, 0, 0);                                         \
    (void)Z4;

#define B16_STORE_A_TR(BUF)                                                          \
    do {                                                                             \
        uint32_t v_[8] = {ra0.x, ra0.y, ra0.z, ra0.w, ra1.x, ra1.y, ra1.z, ra1.w};   \
        _Pragma("unroll")                                                            \
        for (int j_ = 0; j_ < 8; j_++) {                                             \
            int k_ = ak0 + j_;                                                       \
            int p_ = ((k_ & 1) << 3) | (k_ >> 1);                                    \
            As[BUF][p_ * TPW + am] = v_[j_];                                         \
        }                                                                            \
    } while (0)

#define B16_STORE_B_TR(BUF)                                                          \
    do {                                                                             \
        uint32_t v_[8] = {rb0.x, rb0.y, rb0.z, rb0.w, rb1.x, rb1.y, rb1.z, rb1.w};   \
        _Pragma("unroll")                                                            \
        for (int j_ = 0; j_ < 8; j_++) {                                             \
            int k_ = ak0 + j_;                                                       \
            int p_ = ((k_ & 1) << 3) | (k_ >> 1);                                    \
            Bs[BUF][p_ * TPW + am] = v_[j_];                                         \
        }                                                                            \
    } while (0)

#define B16_STORE_B_ROW(BUF, BR0, BC4)                                               \
    do {                                                                             \
        int p0_ = (((BR0) & 1) << 3) | ((BR0) >> 1);                                 \
        *(uint4*)&Bs[BUF][p0_ * TPW + (BC4) * 4] = rb0;                              \
        *(uint4*)&Bs[BUF][(p0_ + 4) * TPW + (BC4) * 4] = rb1;                        \
    } while (0)

#define B16_COMPUTE(CUR)                                                             \
    do {                                                                             \
        const uint32_t* Ac = &As[CUR][0];                                            \
        const uint32_t* Bc = &Bs[CUR][0];                                            \
        int r0 = kc, r1 = 8 + kc, r2 = 4 + kc, r3 = 12 + kc;                         \
        uint32_t ah[2][4], al[2][4];                                                 \
        _Pragma("unroll")                                                            \
        for (int mt = 0; mt < 2; mt++) {                                             \
            int mm = m0 + mt * 16 + fr;                                              \
            uint32_t u0 = Ac[r0 * TPW + mm],     u1 = Ac[r1 * TPW + mm];             \
            uint32_t u2 = Ac[r2 * TPW + mm],     u3 = Ac[r3 * TPW + mm];             \
            uint32_t u4 = Ac[r0 * TPW + mm + 8], u5 = Ac[r1 * TPW + mm + 8];         \
            uint32_t u6 = Ac[r2 * TPW + mm + 8], u7 = Ac[r3 * TPW + mm + 8];         \
            ah[mt][0] = __byte_perm(u0, u1, 0x5410);                                 \
            al[mt][0] = __byte_perm(u0, u1, 0x7632);                                 \
            ah[mt][1] = __byte_perm(u4, u5, 0x5410);                                 \
            al[mt][1] = __byte_perm(u4, u5, 0x7632);                                 \
            ah[mt][2] = __byte_perm(u2, u3, 0x5410);                                 \
            al[mt][2] = __byte_perm(u2, u3, 0x7632);                                 \
            ah[mt][3] = __byte_perm(u6, u7, 0x5410);                                 \
            al[mt][3] = __byte_perm(u6, u7, 0x7632);                                 \
        }                                                                            \
        _Pragma("unroll")                                                            \
        for (int nt = 0; nt < 8; nt++) {                                             \
            int nn = n0 + nt * 8 + fr;                                               \
            uint32_t w0 = Bc[r0 * TPW + nn], w1 = Bc[r1 * TPW + nn];                 \
            uint32_t w2 = Bc[r2 * TPW + nn], w3 = Bc[r3 * TPW + nn];                 \
            uint32_t bh[2], bl[2];                                                   \
            bh[0] = __byte_perm(w0, w1, 0x5410);                                     \
            bl[0] = __byte_perm(w0, w1, 0x7632);                                     \
            bh[1] = __byte_perm(w2, w3, 0x5410);                                     \
            bl[1] = __byte_perm(w2, w3, 0x7632);                                     \
            _Pragma("unroll")                                                        \
            for (int mt = 0; mt < 2; mt++) {                                         \
                mma_bf16(acc[mt][nt], ah[mt], bh);                                   \
                mma_bf16(acc[mt][nt], ah[mt], bl);                                   \
                mma_bf16(acc[mt][nt], al[mt], bh);                                   \
            }                                                                        \
        }                                                                            \
    } while (0)

// ---------------- weight pack-split ----------------
__global__ void cvt_pack(const float* __restrict__ src, uint32_t* __restrict__ dst,
                         long long n) {
    long long i = ((long long)blockIdx.x * blockDim.x + threadIdx.x) * 4;
    if (i >= n) return;
    float4 v = *(const float4*)(src + i);
    uint4 o = make_uint4(packsplit(v.x), packsplit(v.y), packsplit(v.z), packsplit(v.w));
    *(uint4*)(dst + i) = o;
}

// ---------------- generic split-bf16 GEMM (A packed gather, B packed row-major) ----------------
__global__ __launch_bounds__(256, 2)
void gemm_b16(const uint32_t* __restrict__ A, const uint32_t* __restrict__ B,
              float* __restrict__ C,
              int M, int Kd, int lda, int ldb, int ldc,
              const int* __restrict__ rowmap,
              const float* __restrict__ addsrc, float* __restrict__ Cdup,
              const int* __restrict__ segoff, long long strideB,
              const float* __restrict__ rowscale) {
    int row0 = 0, rowEnd = M;
    const uint32_t* Bp = B;
    if (segoff) {
        int e = blockIdx.z;
        row0 = segoff[e];
        rowEnd = segoff[e + 1];
        Bp = B + (long long)e * strideB;
    }
    int rbase = row0 + blockIdx.y * 128;
    if (rbase >= rowEnd) return;
    int cbase = blockIdx.x * 128;

    B16_DECL();
    const uint32_t* Arow = nullptr;
    if (rbase + am < rowEnd) {
        int m = rowmap ? rowmap[rbase + am] : rbase + am;
        Arow = A + (long long)m * lda;
    }
    const uint32_t* Brow_ = Bp + cbase;
    int br0 = tid >> 5, bc4 = tid & 31;

#define LOADG(K0)                                                                    \
    do {                                                                             \
        if (Arow) {                                                                  \
            ra0 = *(const uint4*)(Arow + (K0) + ak0);                                \
            ra1 = *(const uint4*)(Arow + (K0) + ak0 + 4);                            \
        } else { ra0 = Z4; ra1 = Z4; }                                               \
        rb0 = *(const uint4*)(Brow_ + (long long)((K0) + br0) * ldb + bc4 * 4);      \
        rb1 = *(const uint4*)(Brow_ + (long long)((K0) + br0 + 8) * ldb + bc4 * 4);  \
    } while (0)

    int nk = Kd >> 4;
    LOADG(0);
    B16_STORE_A_TR(0);
    B16_STORE_B_ROW(0, br0, bc4);
    __syncthreads();
    for (int kt = 0; kt < nk; kt++) {
        int cur = kt & 1;
        if (kt + 1 < nk) LOADG((kt + 1) * 16);
        B16_COMPUTE(cur);
        if (kt + 1 < nk) {
            B16_STORE_A_TR(cur ^ 1);
            B16_STORE_B_ROW(cur ^ 1, br0, bc4);
            __syncthreads();
        }
    }
#undef LOADG

#pragma unroll
    for (int mt = 0; mt < 2; mt++)
#pragma unroll
        for (int half = 0; half < 2; half++) {
            int row = rbase + m0 + mt * 16 + fr + half * 8;
            if (row >= rowEnd) continue;
            float sc = rowscale ? rowscale[row] : 1.f;
            long long base = (long long)row * ldc + cbase + n0 + 2 * kc;
#pragma unroll
            for (int nt = 0; nt < 8; nt++) {
                long long o = base + nt * 8;
                float2 v = make_float2(acc[mt][nt][half * 2 + 0] * sc,
                                       acc[mt][nt][half * 2 + 1] * sc);
                if (addsrc) {
                    float2 s = *(const float2*)(addsrc + o);
                    v.x += s.x; v.y += s.y;
                }
                *(float2*)(C + o) = v;
                if (Cdup) *(float2*)(Cdup + o) = v;
            }
        }
}

// fused QKV: q,k -> fp32 g_qkv; v -> packed g_vp
__global__ __launch_bounds__(256, 2)
void gemm_b16_qkv(const uint32_t* __restrict__ A) {
    int x = blockIdx.x;
    const uint32_t* Bsel;
    int ldb, bcol;
    if (x < 16)      { Bsel = g_wp + WOFF_Q; ldb = 2048; bcol = x * 128; }
    else if (x < 20) { Bsel = g_wp + WOFF_K; ldb = 512;  bcol = (x - 16) * 128; }
    else             { Bsel = g_wp + WOFF_V; ldb = 512;  bcol = (x - 20) * 128; }
    int rbase = blockIdx.y * 128;

    B16_DECL();
    const uint32_t* Arow = A + (long long)(rbase + am) * H_;
    const uint32_t* Brow_ = Bsel + bcol;
    int br0 = tid >> 5, bc4 = tid & 31;

#define LOADG(K0)                                                                    \
    do {                                                                             \
        ra0 = *(const uint4*)(Arow + (K0) + ak0);                                    \
        ra1 = *(const uint4*)(Arow + (K0) + ak0 + 4);                                \
        rb0 = *(const uint4*)(Brow_ + (long long)((K0) + br0) * ldb + bc4 * 4);      \
        rb1 = *(const uint4*)(Brow_ + (long long)((K0) + br0 + 8) * ldb + bc4 * 4);  \
    } while (0)

    int nk = H_ >> 4;
    LOADG(0);
    B16_STORE_A_TR(0);
    B16_STORE_B_ROW(0, br0, bc4);
    __syncthreads();
    for (int kt = 0; kt < nk; kt++) {
        int cur = kt & 1;
        if (kt + 1 < nk) LOADG((kt + 1) * 16);
        B16_COMPUTE(cur);
        if (kt + 1 < nk) {
            B16_STORE_A_TR(cur ^ 1);
            B16_STORE_B_ROW(cur ^ 1, br0, bc4);
            __syncthreads();
        }
    }
#undef LOADG

#pragma unroll
    for (int mt = 0; mt < 2; mt++)
#pragma unroll
        for (int half = 0; half < 2; half++) {
            int row = rbase + m0 + mt * 16 + fr + half * 8;
            int col = n0 + 2 * kc;
#pragma unroll
            for (int nt = 0; nt < 8; nt++) {
                float v0 = acc[mt][nt][half * 2 + 0];
                float v1 = acc[mt][nt][half * 2 + 1];
                if (x < 20) {
                    long long o = (long long)row * 3072 + x * 128 + col + nt * 8;
                    *(float2*)(g_qkv + o) = make_float2(v0, v1);
                } else {
                    long long o = (long long)row * 512 + (x - 20) * 128 + col + nt * 8;
                    g_vp[o] = packsplit(v0);
                    g_vp[o + 1] = packsplit(v1);
                }
            }
        }
}

// ---------------- attention pass A: S = scale*Q@K^T (packed q/k), causal tiles ----------------
__global__ __launch_bounds__(256, 2)
void gemm_b16_qk() {
    int ktile = blockIdx.x, qtile = blockIdx.y, h = blockIdx.z;
    if (ktile > qtile) return;
    int qbase = qtile * 128, kbase = ktile * 128, kvh = h >> 2;

    B16_DECL();
    const uint32_t* Arow = g_qp + (size_t)(qbase + am) * 2048 + h * DH_;
    const uint32_t* Brow = g_kp + (size_t)(kbase + am) * 512 + kvh * DH_;

#define LOADG(K0)                                                                    \
    do {                                                                             \
        ra0 = *(const uint4*)(Arow + (K0) + ak0);                                    \
        ra1 = *(const uint4*)(Arow + (K0) + ak0 + 4);                                \
        rb0 = *(const uint4*)(Brow + (K0) + ak0);                                    \
        rb1 = *(const uint4*)(Brow + (K0) + ak0 + 4);                                \
    } while (0)

    const int nk = DH_ >> 4;   // 8
    LOADG(0);
    B16_STORE_A_TR(0);
    B16_STORE_B_TR(0);
    __syncthreads();
    for (int kt = 0; kt < nk; kt++) {
        int cur = kt & 1;
        if (kt + 1 < nk) LOADG((kt + 1) * 16);
        B16_COMPUTE(cur);
        if (kt + 1 < nk) {
            B16_STORE_A_TR(cur ^ 1);
            B16_STORE_B_TR(cur ^ 1);
            __syncthreads();
        }
    }
#undef LOADG

    const float scale = 0.08838834764831845f;
#pragma unroll
    for (int mt = 0; mt < 2; mt++)
#pragma unroll
        for (int half = 0; half < 2; half++) {
            int q = qbase + m0 + mt * 16 + fr + half * 8;
            float* srow = g_s + ((size_t)h * T_ + q) * T_ + kbase + n0 + 2 * kc;
            int k0 = kbase + n0 + 2 * kc;
#pragma unroll
            for (int nt = 0; nt < 8; nt++) {
                float v0 = (k0 + nt * 8 + 0 <= q) ? acc[mt][nt][half * 2 + 0] * scale : -1e30f;
                float v1 = (k0 + nt * 8 + 1 <= q) ? acc[mt][nt][half * 2 + 1] * scale : -1e30f;
                *(float2*)(srow + nt * 8) = make_float2(v0, v1);
            }
        }
}

// ---------------- attention pass B: softmax, writes PACKED probs in place ----------------
__global__ __launch_bounds__(256)
void softmax_rows() {
    int q = blockIdx.x, h = blockIdx.y;
    float* row = g_s + ((size_t)h * T_ + q) * T_;
    uint32_t* prow = (uint32_t*)row;
    int L = q + 1, pad_end = ((q >> 7) + 1) << 7, tid = threadIdx.x;
    float v[8];
    int nchunk = (L + 255) >> 8;
    float mx = -1e30f;
#pragma unroll 4
    for (int c = 0; c < nchunk; c++) {
        int i = c * 256 + tid;
        v[c] = (i < L) ? row[i] : -1e30f;
        mx = fmaxf(mx, v[c]);
    }
    mx = block_reduce_max(mx);
    float s = 0.f;
#pragma unroll 4
    for (int c = 0; c < nchunk; c++) { v[c] = __expf(v[c] - mx); s += v[c]; }
    float tot = block_reduce_sum(s);
    float inv = 1.f / tot;
#pragma unroll 4
    for (int c = 0; c < nchunk; c++) {
        int i = c * 256 + tid;
        if (i < L) prow[i] = packsplit(v[c] * inv);
    }
    for (int i = L + tid; i < pad_end; i += 256) prow[i] = 0u;
}

// ---------------- attention pass C: O = P @ V -> packed g_attnp ----------------
__global__ __launch_bounds__(256, 2)
void gemm_b16_pv() {
    int qt = (int)gridDim.x - 1 - (int)blockIdx.x;   // longest first
    int h = blockIdx.y;
    int rbase = qt * 128, kvh = h >> 2;

    B16_DECL();
    const uint32_t* Arow = (const uint32_t*)g_s + (size_t)h * T_ * T_ +
                           (size_t)(rbase + am) * T_;
    const uint32_t* Bp = g_vp + kvh * DH_;           // row stride 512
    int br0 = tid >> 5, bc4 = tid & 31;

#define LOADG(K0)                                                                    \
    do {                                                                             \
        ra0 = *(const uint4*)(Arow + (K0) + ak0);                                    \
        ra1 = *(const uint4*)(Arow + (K0) + ak0 + 4);                                \
        rb0 = *(const uint4*)(Bp + (size_t)((K0) + br0) * 512 + bc4 * 4);            \
        rb1 = *(const uint4*)(Bp + (size_t)((K0) + br0 + 8) * 512 + bc4 * 4);        \
    } while (0)

    int nk = (qt + 1) * 8;
    LOADG(0);
    B16_STORE_A_TR(0);
    B16_STORE_B_ROW(0, br0, bc4);
    __syncthreads();
    for (int kt = 0; kt < nk; kt++) {
        int cur = kt & 1;
        if (kt + 1 < nk) LOADG((kt + 1) * 16);
        B16_COMPUTE(cur);
        if (kt + 1 < nk) {
            B16_STORE_A_TR(cur ^ 1);
            B16_STORE_B_ROW(cur ^ 1, br0, bc4);
            __syncthreads();
        }
    }
#undef LOADG

#pragma unroll
    for (int mt = 0; mt < 2; mt++)
#pragma unroll
        for (int half = 0; half < 2; half++) {
            int q = rbase + m0 + mt * 16 + fr + half * 8;
            size_t base = (size_t)q * H_ + h * DH_ + n0 + 2 * kc;
#pragma unroll
            for (int nt = 0; nt < 8; nt++) {
                g_attnp[base + nt * 8] = packsplit(acc[mt][nt][half * 2 + 0]);
                g_attnp[base + nt * 8 + 1] = packsplit(acc[mt][nt][half * 2 + 1]);
            }
        }
}

// ---------------- elementwise ----------------
__global__ void embcat_kernel(const int* __restrict__ ids,
                              const float* __restrict__ emb_w,
                              const float* __restrict__ hid,
                              const float* __restrict__ we,
                              const float* __restrict__ wh) {
    int t = blockIdx.x;
    const float* er = emb_w + (size_t)ids[t] * H_;
    const float* hr = hid + (size_t)t * H_;
    uint32_t* cp = g_catp + (size_t)t * 2 * H_;
    float ss = 0.f;
    for (int h = threadIdx.x; h < H_; h += blockDim.x) { float v = er[h]; ss += v * v; }
    float rs = rsqrtf(block_reduce_sum(ss) / H_ + EPS_);
    for (int h = threadIdx.x; h < H_; h += blockDim.x)
        cp[h] = packsplit(er[h] * rs * (1.f + we[h]));
    ss = 0.f;
    for (int h = threadIdx.x; h < H_; h += blockDim.x) { float v = hr[h]; ss += v * v; }
    rs = rsqrtf(block_reduce_sum(ss) / H_ + EPS_);
    for (int h = threadIdx.x; h < H_; h += blockDim.x)
        cp[H_ + h] = packsplit(hr[h] * rs * (1.f + wh[h]));
}

__global__ void rmsnorm_kernel(const float* __restrict__ in,
                               const float* __restrict__ w,
                               float* __restrict__ outf,
                               uint32_t* __restrict__ outp) {
    int t = blockIdx.x;
    const float* r = in + (size_t)t * H_;
    float ss = 0.f;
    for (int h = threadIdx.x; h < H_; h += blockDim.x) { float v = r[h]; ss += v * v; }
    float rs = rsqrtf(block_reduce_sum(ss) / H_ + EPS_);
    for (int h = threadIdx.x; h < H_; h += blockDim.x) {
        float v = r[h] * rs * (1.f + w[h]);
        if (outf) outf[(size_t)t * H_ + h] = v;
        outp[(size_t)t * H_ + h] = packsplit(v);
    }
}

// per-head rms + rope: read fp32 g_qkv, write packed plane
__global__ void qkrope_kernel(int coloff, uint32_t* __restrict__ outp, int ostride,
                              const float* __restrict__ nw,
                              const int* __restrict__ positions) {
    int t = blockIdx.x, h = blockIdx.y;
    const float* v = g_qkv + (size_t)t * 3072 + coloff + h * DH_;
    int d = threadIdx.x;
    float val = v[d];
    float ss = val * val;
#pragma unroll
    for (int o = 16; o > 0; o >>= 1) ss += __shfl_xor_sync(0xffffffffu, ss, o);
    __shared__ float ws[4];
    if ((d & 31) == 0) ws[d >> 5] = ss;
    __syncthreads();
    float rs = rsqrtf((ws[0] + ws[1] + ws[2] + ws[3]) / DH_ + EPS_);
    float n = val * rs * (1.f + nw[d]);
    __shared__ float nv[DH_];
    nv[d] = n;
    __syncthreads();
    int pos = positions[t];
    int i = d & 63;
    float inv = expf(-((float)i / 64.f) * 13.815510557964274f);
    float ang = (float)pos * inv;
    float c = cosf(ang), s = sinf(ang);
    float outv = (d < 64) ? nv[d] * c - nv[d + 64] * s : nv[d] * c + nv[d - 64] * s;
    outp[(size_t)t * ostride + h * DH_ + d] = packsplit(outv);
}

__global__ void zero_counts_kernel() { if (threadIdx.x < E_) g_counts[threadIdx.x] = 0; }

__global__ void router_kernel(const float* __restrict__ rw) {
    int t = blockIdx.x;
    __shared__ float part[256];
    __shared__ float logits[E_];
    int tid = threadIdx.x, e = tid >> 4, c = tid & 15;
    float s = 0.f;
    const float* xr = g_xn + (size_t)t * H_;
    for (int h = c * 128; h < (c + 1) * 128; h++) s += xr[h] * rw[(size_t)h * E_ + e];
    part[tid] = s;
    __syncthreads();
    if (c == 0) {
        float tot = 0.f;
        for (int i = 0; i < 16; i++) tot += part[e * 16 + i];
        logits[e] = tot;
    }
    __syncthreads();
    if (tid == 0) {
        float mx = -1e30f;
        for (int i = 0; i < E_; i++) mx = fmaxf(mx, logits[i]);
        float p[E_];
        for (int i = 0; i < E_; i++) p[i] = expf(logits[i] - mx);
        int i0 = 0; float v0 = p[0];
        for (int i = 1; i < E_; i++) if (p[i] > v0) { v0 = p[i]; i0 = i; }
        int i1 = -1; float v1 = -1.f;
        for (int i = 0; i < E_; i++) if (i != i0 && p[i] > v1) { v1 = p[i]; i1 = i; }
        float denom = v0 + v1;
        g_top_idx[t * 2 + 0] = i0; g_top_idx[t * 2 + 1] = i1;
        g_top_w[t * 2 + 0] = v0 / denom; g_top_w[t * 2 + 1] = v1 / denom;
        atomicAdd(&g_counts[i0], 1);
        atomicAdd(&g_counts[i1], 1);
    }
}

__global__ void offsets_kernel() {
    if (threadIdx.x == 0) {
        int acc = 0;
        for (int e = 0; e < E_; e++) { g_offs[e] = acc; acc += g_counts[e]; }
        g_offs[E_] = acc;
    }
    if (threadIdx.x < E_) g_counts2[threadIdx.x] = 0;
}

__global__ void scatter_kernel() {
    int t = blockIdx.x * blockDim.x + threadIdx.x;
    if (t >= T_) return;
    for (int k = 0; k < TOPK_; k++) {
        int e = g_top_idx[t * 2 + k];
        int pos = atomicAdd(&g_counts2[e], 1);
        int slot = g_offs[e] + pos;
        g_tok_of_slot[slot] = t;
        g_gate_of_slot[slot] = g_top_w[t * 2 + k];
        g_slot_of_tok[t * 2 + k] = slot;
    }
}

__global__ void silu_mul_kernel() {
    size_t i = (size_t)blockIdx.x * blockDim.x + threadIdx.x;
    if (i >= (size_t)T_ * TOPK_ * I_) return;
    float x = g_gbuf[i];
    g_actp[i] = packsplit((x / (1.f + expf(-x))) * g_ubuf[i]);
}

__global__ void final_kernel(const float* __restrict__ fw, float* __restrict__ out) {
    int t = blockIdx.x;
    __shared__ float buf[H_];
    int s0 = g_slot_of_tok[t * 2 + 0], s1 = g_slot_of_tok[t * 2 + 1];
    float ss = 0.f;
    for (int h = threadIdx.x; h < H_; h += blockDim.x) {
        float v = g_x[(size_t)t * H_ + h] + g_downbuf[(size_t)s0 * H_ + h] +
                  g_downbuf[(size_t)s1 * H_ + h];
        buf[h] = v;
        ss += v * v;
    }
    float rs = rsqrtf(block_reduce_sum(ss) / H_ + EPS_);
    for (int h = threadIdx.x; h < H_; h += blockDim.x)
        out[(size_t)t * H_ + h] = buf[h] * rs * (1.f + fw[h]);
}

// ---------------- launch ----------------
extern "C" void kernel_launch(void* const* d_in, const int* in_sizes, int n_in,
                              void* d_out, int out_size) {
    const int* input_ids      = (const int*)d_in[0];
    const int* positions      = (const int*)d_in[1];
    const float* hidden       = (const float*)d_in[2];
    const float* embed_w      = (const float*)d_in[4];
    const float* fc_w         = (const float*)d_in[5];
    const float* pre_fc_emb_w = (const float*)d_in[6];
    const float* pre_fc_hid_w = (const float*)d_in[7];
    const float* in_ln_w      = (const float*)d_in[8];
    const float* post_ln_w    = (const float*)d_in[9];
    const float* final_norm_w = (const float*)d_in[10];
    const float* wq           = (const float*)d_in[11];
    const float* wk           = (const float*)d_in[12];
    const float* wv           = (const float*)d_in[13];
    const float* wo           = (const float*)d_in[14];
    const float* q_norm_w     = (const float*)d_in[15];
    const float* k_norm_w     = (const float*)d_in[16];
    const float* router_w     = (const float*)d_in[17];
    const float* w_gate       = (const float*)d_in[18];
    const float* w_up         = (const float*)d_in[19];
    const float* w_down       = (const float*)d_in[20];
    float* out = (float*)d_out;

    float *p_x, *p_res, *p_xn, *p_g, *p_u, *p_down, *p_gate;
    int *p_tok, *p_offs;
    uint32_t *p_wp, *p_catp, *p_xnp, *p_qp, *p_kp, *p_attnp, *p_actp;
    cudaGetSymbolAddress((void**)&p_x, g_x);
    cudaGetSymbolAddress((void**)&p_res, g_res);
    cudaGetSymbolAddress((void**)&p_xn, g_xn);
    cudaGetSymbolAddress((void**)&p_g, g_gbuf);
    cudaGetSymbolAddress((void**)&p_u, g_ubuf);
    cudaGetSymbolAddress((void**)&p_down, g_downbuf);
    cudaGetSymbolAddress((void**)&p_gate, g_gate_of_slot);
    cudaGetSymbolAddress((void**)&p_tok, g_tok_of_slot);
    cudaGetSymbolAddress((void**)&p_offs, g_offs);
    cudaGetSymbolAddress((void**)&p_wp, g_wp);
    cudaGetSymbolAddress((void**)&p_catp, g_catp);
    cudaGetSymbolAddress((void**)&p_xnp, g_xnp);
    cudaGetSymbolAddress((void**)&p_qp, g_qp);
    cudaGetSymbolAddress((void**)&p_kp, g_kp);
    cudaGetSymbolAddress((void**)&p_attnp, g_attnp);
    cudaGetSymbolAddress((void**)&p_actp, g_actp);

    // 0. weight pack-split (per launch; weights are harness inputs)
    struct WC { const float* s; long long off, n; };
    const WC wc[8] = {
        {fc_w, WOFF_FC, 8388608LL},  {wq, WOFF_Q, 4194304LL},
        {wk, WOFF_K, 1048576LL},     {wv, WOFF_V, 1048576LL},
        {wo, WOFF_O, 4194304LL},     {w_gate, WOFF_G, 33554432LL},
        {w_up, WOFF_U, 33554432LL},  {w_down, WOFF_D, 33554432LL},
    };
    for (int i = 0; i < 8; i++) {
        long long nthr = wc[i].n / 4;
        cvt_pack<<<(unsigned)((nthr + 255) / 256), 256>>>(wc[i].s, p_wp + wc[i].off,
                                                          wc[i].n);
    }

    // 1. embed + rms -> packed cat
    embcat_kernel<<<T_, 256>>>(input_ids, embed_w, hidden, pre_fc_emb_w, pre_fc_hid_w);

    // 2. fc: x = cat @ fc_w ; residual = x
    gemm_b16<<<dim3(H_ / 128, T_ / 128), 256>>>(p_catp, p_wp + WOFF_FC, p_x,
                                                T_, 2 * H_, 2 * H_, H_, H_,
                                                nullptr, nullptr, p_res, nullptr, 0, nullptr);

    // 3. in_ln -> packed (+fp32 unused path ok)
    rmsnorm_kernel<<<T_, 256>>>(p_x, in_ln_w, nullptr, p_xnp);

    // 4. fused qkv: q,k fp32 -> g_qkv ; v packed -> g_vp
    gemm_b16_qkv<<<dim3(24, T_ / 128), 256>>>(p_xnp);

    // 5. q/k norm + rope -> packed planes
    qkrope_kernel<<<dim3(T_, NH_), DH_>>>(0, p_qp, NH_ * DH_, q_norm_w, positions);
    qkrope_kernel<<<dim3(T_, NKV_), DH_>>>(2048, p_kp, NKV_ * DH_, k_norm_w, positions);

    // 6. attention: QK^T -> softmax(pack) -> PV
    gemm_b16_qk<<<dim3(T_ / 128, T_ / 128, NH_), 256>>>();
    softmax_rows<<<dim3(T_, NH_), 256>>>();
    gemm_b16_pv<<<dim3(T_ / 128, NH_), 256>>>();

    // 7. wo + residual -> x
    gemm_b16<<<dim3(H_ / 128, T_ / 128), 256>>>(p_attnp, p_wp + WOFF_O, p_x,
                                                T_, NH_ * DH_, NH_ * DH_, H_, H_,
                                                nullptr, p_res, nullptr, nullptr, 0, nullptr);

    // 8. post_ln -> fp32 (router) + packed (MoE)
    rmsnorm_kernel<<<T_, 256>>>(p_x, post_ln_w, p_xn, p_xnp);

    // 9. router + bucketing
    zero_counts_kernel<<<1, 32>>>();
    router_kernel<<<T_, 256>>>(router_w);
    offsets_kernel<<<1, 32>>>();
    scatter_kernel<<<(T_ + 255) / 256, 256>>>();

    // 10. MoE grouped GEMMs
    gemm_b16<<<dim3(I_ / 128, T_ / 128, E_), 256>>>(p_xnp, p_wp + WOFF_G, p_g,
                                                    0, H_, H_, I_, I_,
                                                    p_tok, nullptr, nullptr, p_offs,
                                                    (long long)H_ * I_, nullptr);
    gemm_b16<<<dim3(I_ / 128, T_ / 128, E_), 256>>>(p_xnp, p_wp + WOFF_U, p_u,
                                                    0, H_, H_, I_, I_,
                                                    p_tok, nullptr, nullptr, p_offs,
                                                    (long long)H_ * I_, nullptr);
    silu_mul_kernel<<<((size_t)T_ * TOPK_ * I_ + 255) / 256, 256>>>();
    gemm_b16<<<dim3(H_ / 128, T_ / 128, E_), 256>>>(p_actp, p_wp + WOFF_D, p_down,
                                                    0, I_, I_, H_, H_,
                                                    nullptr, nullptr, nullptr, p_offs,
                                                    (long long)I_ * H_, p_gate);

    // 11. combine + final rms
    final_kernel<<<T_, 256>>>(final_norm_w, out);
}

// round 16
// speedup vs baseline: 1.7712x; 1.0129x over previous
#include <cuda_runtime.h>
#include <cuda_bf16.h>
#include <math.h>
#include <stdint.h>

#define T_ 2048
#define H_ 2048
#define NH_ 16
#define NKV_ 4
#define DH_ 128
#define E_ 16
#define TOPK_ 2
#define I_ 1024
#define EPS_ 1e-6f

// ---------------- fp32 scratch ----------------
__device__ float g_x[(size_t)T_ * H_];
__device__ float g_res[(size_t)T_ * H_];
__device__ float g_xn[(size_t)T_ * H_];
__device__ float g_qkv[(size_t)T_ * 3072];          // q,k fp32 (pre-rope)
__device__ float g_s[(size_t)NH_ * T_ * T_];        // scores fp32 -> packed probs in place
__device__ float g_gbuf[(size_t)T_ * TOPK_ * I_];
__device__ float g_ubuf[(size_t)T_ * TOPK_ * I_];
__device__ float g_downbuf[(size_t)T_ * TOPK_ * H_];
__device__ int   g_top_idx[T_ * TOPK_];
__device__ float g_top_w[T_ * TOPK_];
__device__ int   g_counts[E_];
__device__ int   g_counts2[E_];
__device__ int   g_offs[E_ + 1];
__device__ int   g_tok_of_slot[T_ * TOPK_];
__device__ float g_gate_of_slot[T_ * TOPK_];
__device__ int   g_slot_of_tok[T_ * TOPK_];

// ---------------- packed (hi,lo) bf16 activation planes ----------------
__device__ uint32_t g_catp[(size_t)T_ * 2 * H_];
__device__ uint32_t g_xnp[(size_t)T_ * H_];
__device__ uint32_t g_qp[(size_t)T_ * NH_ * DH_];
__device__ uint32_t g_kp[(size_t)T_ * NKV_ * DH_];
__device__ uint32_t g_vp[(size_t)T_ * NKV_ * DH_];
__device__ uint32_t g_attnp[(size_t)T_ * H_];
__device__ uint32_t g_actp[(size_t)T_ * TOPK_ * I_];

// ---------------- helpers ----------------
__device__ __forceinline__ float block_reduce_sum(float v) {
    __shared__ float sb[33];
    int tid = threadIdx.x;
#pragma unroll
    for (int o = 16; o > 0; o >>= 1) v += __shfl_xor_sync(0xffffffffu, v, o);
    if ((tid & 31) == 0) sb[tid >> 5] = v;
    __syncthreads();
    if (tid == 0) {
        float s = 0.f;
        int nw = (blockDim.x + 31) >> 5;
        for (int i = 0; i < nw; i++) s += sb[i];
        sb[32] = s;
    }
    __syncthreads();
    return sb[32];
}
__device__ __forceinline__ float block_reduce_max(float v) {
    __shared__ float sb[33];
    int tid = threadIdx.x;
#pragma unroll
    for (int o = 16; o > 0; o >>= 1) v = fmaxf(v, __shfl_xor_sync(0xffffffffu, v, o));
    if ((tid & 31) == 0) sb[tid >> 5] = v;
    __syncthreads();
    if (tid == 0) {
        float s = -1e30f;
        int nw = (blockDim.x + 31) >> 5;
        for (int i = 0; i < nw; i++) s = fmaxf(s, sb[i]);
        sb[32] = s;
    }
    __syncthreads();
    return sb[32];
}

__device__ __forceinline__ uint32_t packsplit(float x) {
    __nv_bfloat16 h = __float2bfloat16_rn(x);
    float hf = __bfloat162float(h);
    __nv_bfloat16 l = __float2bfloat16_rn(x - hf);
    return (uint32_t)__bfloat16_as_ushort(h) |
           ((uint32_t)__bfloat16_as_ushort(l) << 16);
}
__device__ __forceinline__ void mma_bf16(float* d, const uint32_t* a, const uint32_t* b) {
    asm volatile("mma.sync.aligned.m16n8k16.row.col.f32.bf16.bf16.f32 "
                 "{%0,%1,%2,%3}, {%4,%5,%6,%7}, {%8,%9}, {%0,%1,%2,%3};"
                 : "+f"(d[0]), "+f"(d[1]), "+f"(d[2]), "+f"(d[3])
                 : "r"(a[0]), "r"(a[1]), "r"(a[2]), "r"(a[3]), "r"(b[0]), "r"(b[1]));
}

#define TPW 136  // word pitch; 136 % 32 = 8 -> conflict-free with k-row permutation

// k-row permutation: logical k -> physical row (k&1)*8 + (k>>1)
#define B16_DECL()                                                                   \
    __shared__ uint32_t As[2][16 * TPW];                                             \
    __shared__ uint32_t Bs[2][16 * TPW];                                             \
    int tid = threadIdx.x, lane = tid & 31, wid = tid >> 5;                          \
    int m0 = (wid & 3) * 32, n0 = (wid >> 2) * 64;                                   \
    int fr = lane >> 2, kc = lane & 3;                                               \
    int am = tid & 127, ak0 = (tid >> 7) * 8;                                        \
    float acc[2][8][4];                                                              \
    _Pragma("unroll") for (int i_ = 0; i_ < 2; i_++)                                 \
        _Pragma("unroll") for (int j_ = 0; j_ < 8; j_++)                             \
            _Pragma("unroll") for (int c_ = 0; c_ < 4; c_++) acc[i_][j_][c_] = 0.f;  \
    uint4 ra0, ra1, rb0, rb1;                                                        \
    float4 fb0, fb1;                                                                 \
    const uint4 Z4 = make_uint4(0, 0, 0, 0);                                         \
    (void)Z4; (void)rb0; (void)rb1; (void)fb0; (void)fb1;

#define B16_STORE_A_TR(BUF)                                                          \
    do {                                                                             \
        uint32_t v_[8] = {ra0.x, ra0.y, ra0.z, ra0.w, ra1.x, ra1.y, ra1.z, ra1.w};   \
        _Pragma("unroll")                                                            \
        for (int j_ = 0; j_ < 8; j_++) {                                             \
            int k_ = ak0 + j_;                                                       \
            int p_ = ((k_ & 1) << 3) | (k_ >> 1);                                    \
            As[BUF][p_ * TPW + am] = v_[j_];                                         \
        }                                                                            \
    } while (0)

#define B16_STORE_B_TR(BUF)                                                          \
    do {                                                                             \
        uint32_t v_[8] = {rb0.x, rb0.y, rb0.z, rb0.w, rb1.x, rb1.y, rb1.z, rb1.w};   \
        _Pragma("unroll")                                                            \
        for (int j_ = 0; j_ < 8; j_++) {                                             \
            int k_ = ak0 + j_;                                                       \
            int p_ = ((k_ & 1) << 3) | (k_ >> 1);                                    \
            Bs[BUF][p_ * TPW + am] = v_[j_];                                         \
        }                                                                            \
    } while (0)

// packed B row store (pv: B already packed)
#define B16_STORE_B_ROW(BUF, BR0, BC4)                                               \
    do {                                                                             \
        int p0_ = (((BR0) & 1) << 3) | ((BR0) >> 1);                                 \
        *(uint4*)&Bs[BUF][p0_ * TPW + (BC4) * 4] = rb0;                              \
        *(uint4*)&Bs[BUF][(p0_ + 4) * TPW + (BC4) * 4] = rb1;                        \
    } while (0)

// fp32 B row store with in-register split (weight GEMMs)
#define B16_STORE_B_ROWF(BUF, BR0, BC4)                                              \
    do {                                                                             \
        int p0_ = (((BR0) & 1) << 3) | ((BR0) >> 1);                                 \
        uint4 o0_ = make_uint4(packsplit(fb0.x), packsplit(fb0.y),                   \
                               packsplit(fb0.z), packsplit(fb0.w));                  \
        *(uint4*)&Bs[BUF][p0_ * TPW + (BC4) * 4] = o0_;                              \
        uint4 o1_ = make_uint4(packsplit(fb1.x), packsplit(fb1.y),                   \
                               packsplit(fb1.z), packsplit(fb1.w));                  \
        *(uint4*)&Bs[BUF][(p0_ + 4) * TPW + (BC4) * 4] = o1_;                        \
    } while (0)

#define B16_COMPUTE(CUR)                                                             \
    do {                                                                             \
        const uint32_t* Ac = &As[CUR][0];                                            \
        const uint32_t* Bc = &Bs[CUR][0];                                            \
        int r0 = kc, r1 = 8 + kc, r2 = 4 + kc, r3 = 12 + kc;                         \
        uint32_t ah[2][4], al[2][4];                                                 \
        _Pragma("unroll")                                                            \
        for (int mt = 0; mt < 2; mt++) {                                             \
            int mm = m0 + mt * 16 + fr;                                              \
            uint32_t u0 = Ac[r0 * TPW + mm],     u1 = Ac[r1 * TPW + mm];             \
            uint32_t u2 = Ac[r2 * TPW + mm],     u3 = Ac[r3 * TPW + mm];             \
            uint32_t u4 = Ac[r0 * TPW + mm + 8], u5 = Ac[r1 * TPW + mm + 8];         \
            uint32_t u6 = Ac[r2 * TPW + mm + 8], u7 = Ac[r3 * TPW + mm + 8];         \
            ah[mt][0] = __byte_perm(u0, u1, 0x5410);                                 \
            al[mt][0] = __byte_perm(u0, u1, 0x7632);                                 \
            ah[mt][1] = __byte_perm(u4, u5, 0x5410);                                 \
            al[mt][1] = __byte_perm(u4, u5, 0x7632);                                 \
            ah[mt][2] = __byte_perm(u2, u3, 0x5410);                                 \
            al[mt][2] = __byte_perm(u2, u3, 0x7632);                                 \
            ah[mt][3] = __byte_perm(u6, u7, 0x5410);                                 \
            al[mt][3] = __byte_perm(u6, u7, 0x7632);                                 \
        }                                                                            \
        _Pragma("unroll")                                                            \
        for (int nt = 0; nt < 8; nt++) {                                             \
            int nn = n0 + nt * 8 + fr;                                               \
            uint32_t w0 = Bc[r0 * TPW + nn], w1 = Bc[r1 * TPW + nn];                 \
            uint32_t w2 = Bc[r2 * TPW + nn], w3 = Bc[r3 * TPW + nn];                 \
            uint32_t bh[2], bl[2];                                                   \
            bh[0] = __byte_perm(w0, w1, 0x5410);                                     \
            bl[0] = __byte_perm(w0, w1, 0x7632);                                     \
            bh[1] = __byte_perm(w2, w3, 0x5410);                                     \
            bl[1] = __byte_perm(w2, w3, 0x7632);                                     \
            _Pragma("unroll")                                                        \
            for (int mt = 0; mt < 2; mt++) {                                         \
                mma_bf16(acc[mt][nt], ah[mt], bh);                                   \
                mma_bf16(acc[mt][nt], ah[mt], bl);                                   \
                mma_bf16(acc[mt][nt], al[mt], bh);                                   \
            }                                                                        \
        }                                                                            \
    } while (0)

// ---------------- split-bf16 GEMM (A packed gather, B fp32 weights split at staging) ----------------
__global__ __launch_bounds__(256, 2)
void gemm_b16(const uint32_t* __restrict__ A, const float* __restrict__ B,
              float* __restrict__ C,
              int M, int Kd, int lda, int ldb, int ldc,
              const int* __restrict__ rowmap,
              const float* __restrict__ addsrc, float* __restrict__ Cdup,
              const int* __restrict__ segoff, long long strideB,
              const float* __restrict__ rowscale) {
    int row0 = 0, rowEnd = M;
    const float* Bp = B;
    if (segoff) {
        int e = blockIdx.z;
        row0 = segoff[e];
        rowEnd = segoff[e + 1];
        Bp = B + (long long)e * strideB;
    }
    int rbase = row0 + blockIdx.y * 128;
    if (rbase >= rowEnd) return;
    int cbase = blockIdx.x * 128;

    B16_DECL();
    const uint32_t* Arow = nullptr;
    if (rbase + am < rowEnd) {
        int m = rowmap ? rowmap[rbase + am] : rbase + am;
        Arow = A + (long long)m * lda;
    }
    const float* Brow_ = Bp + cbase;
    int br0 = tid >> 5, bc4 = tid & 31;

#define LOADG(K0)                                                                    \
    do {                                                                             \
        if (Arow) {                                                                  \
            ra0 = *(const uint4*)(Arow + (K0) + ak0);                                \
            ra1 = *(const uint4*)(Arow + (K0) + ak0 + 4);                            \
        } else { ra0 = Z4; ra1 = Z4; }                                               \
        fb0 = *(const float4*)(Brow_ + (long long)((K0) + br0) * ldb + bc4 * 4);     \
        fb1 = *(const float4*)(Brow_ + (long long)((K0) + br0 + 8) * ldb + bc4 * 4); \
    } while (0)

    int nk = Kd >> 4;
    LOADG(0);
    B16_STORE_A_TR(0);
    B16_STORE_B_ROWF(0, br0, bc4);
    __syncthreads();
    for (int kt = 0; kt < nk; kt++) {
        int cur = kt & 1;
        if (kt + 1 < nk) LOADG((kt + 1) * 16);
        B16_COMPUTE(cur);
        if (kt + 1 < nk) {
            B16_STORE_A_TR(cur ^ 1);
            B16_STORE_B_ROWF(cur ^ 1, br0, bc4);
            __syncthreads();
        }
    }
#undef LOADG

#pragma unroll
    for (int mt = 0; mt < 2; mt++)
#pragma unroll
        for (int half = 0; half < 2; half++) {
            int row = rbase + m0 + mt * 16 + fr + half * 8;
            if (row >= rowEnd) continue;
            float sc = rowscale ? rowscale[row] : 1.f;
            long long base = (long long)row * ldc + cbase + n0 + 2 * kc;
#pragma unroll
            for (int nt = 0; nt < 8; nt++) {
                long long o = base + nt * 8;
                float2 v = make_float2(acc[mt][nt][half * 2 + 0] * sc,
                                       acc[mt][nt][half * 2 + 1] * sc);
                if (addsrc) {
                    float2 s = *(const float2*)(addsrc + o);
                    v.x += s.x; v.y += s.y;
                }
                *(float2*)(C + o) = v;
                if (Cdup) *(float2*)(Cdup + o) = v;
            }
        }
}

// fused QKV: q,k -> fp32 g_qkv; v -> packed g_vp (weights fp32, split at staging)
__global__ __launch_bounds__(256, 2)
void gemm_b16_qkv(const uint32_t* __restrict__ A,
                  const float* __restrict__ wq, const float* __restrict__ wk,
                  const float* __restrict__ wv) {
    int x = blockIdx.x;
    const float* Bsel;
    int ldb, bcol;
    if (x < 16)      { Bsel = wq; ldb = 2048; bcol = x * 128; }
    else if (x < 20) { Bsel = wk; ldb = 512;  bcol = (x - 16) * 128; }
    else             { Bsel = wv; ldb = 512;  bcol = (x - 20) * 128; }
    int rbase = blockIdx.y * 128;

    B16_DECL();
    const uint32_t* Arow = A + (long long)(rbase + am) * H_;
    const float* Brow_ = Bsel + bcol;
    int br0 = tid >> 5, bc4 = tid & 31;

#define LOADG(K0)                                                                    \
    do {                                                                             \
        ra0 = *(const uint4*)(Arow + (K0) + ak0);                                    \
        ra1 = *(const uint4*)(Arow + (K0) + ak0 + 4);                                \
        fb0 = *(const float4*)(Brow_ + (long long)((K0) + br0) * ldb + bc4 * 4);     \
        fb1 = *(const float4*)(Brow_ + (long long)((K0) + br0 + 8) * ldb + bc4 * 4); \
    } while (0)

    int nk = H_ >> 4;
    LOADG(0);
    B16_STORE_A_TR(0);
    B16_STORE_B_ROWF(0, br0, bc4);
    __syncthreads();
    for (int kt = 0; kt < nk; kt++) {
        int cur = kt & 1;
        if (kt + 1 < nk) LOADG((kt + 1) * 16);
        B16_COMPUTE(cur);
        if (kt + 1 < nk) {
            B16_STORE_A_TR(cur ^ 1);
            B16_STORE_B_ROWF(cur ^ 1, br0, bc4);
            __syncthreads();
        }
    }
#undef LOADG

#pragma unroll
    for (int mt = 0; mt < 2; mt++)
#pragma unroll
        for (int half = 0; half < 2; half++) {
            int row = rbase + m0 + mt * 16 + fr + half * 8;
            int col = n0 + 2 * kc;
#pragma unroll
            for (int nt = 0; nt < 8; nt++) {
                float v0 = acc[mt][nt][half * 2 + 0];
                float v1 = acc[mt][nt][half * 2 + 1];
                if (x < 20) {
                    long long o = (long long)row * 3072 + x * 128 + col + nt * 8;
                    *(float2*)(g_qkv + o) = make_float2(v0, v1);
                } else {
                    long long o = (long long)row * 512 + (x - 20) * 128 + col + nt * 8;
                    g_vp[o] = packsplit(v0);
                    g_vp[o + 1] = packsplit(v1);
                }
            }
        }
}

// ---------------- attention pass A: S = scale*Q@K^T (packed q/k), causal tiles ----------------
__global__ __launch_bounds__(256, 2)
void gemm_b16_qk() {
    int ktile = blockIdx.x, qtile = blockIdx.y, h = blockIdx.z;
    if (ktile > qtile) return;
    int qbase = qtile * 128, kbase = ktile * 128, kvh = h >> 2;

    B16_DECL();
    const uint32_t* Arow = g_qp + (size_t)(qbase + am) * 2048 + h * DH_;
    const uint32_t* Brow = g_kp + (size_t)(kbase + am) * 512 + kvh * DH_;

#define LOADG(K0)                                                                    \
    do {                                                                             \
        ra0 = *(const uint4*)(Arow + (K0) + ak0);                                    \
        ra1 = *(const uint4*)(Arow + (K0) + ak0 + 4);                                \
        rb0 = *(const uint4*)(Brow + (K0) + ak0);                                    \
        rb1 = *(const uint4*)(Brow + (K0) + ak0 + 4);                                \
    } while (0)

    const int nk = DH_ >> 4;   // 8
    LOADG(0);
    B16_STORE_A_TR(0);
    B16_STORE_B_TR(0);
    __syncthreads();
    for (int kt = 0; kt < nk; kt++) {
        int cur = kt & 1;
        if (kt + 1 < nk) LOADG((kt + 1) * 16);
        B16_COMPUTE(cur);
        if (kt + 1 < nk) {
            B16_STORE_A_TR(cur ^ 1);
            B16_STORE_B_TR(cur ^ 1);
            __syncthreads();
        }
    }
#undef LOADG

    const float scale = 0.08838834764831845f;
#pragma unroll
    for (int mt = 0; mt < 2; mt++)
#pragma unroll
        for (int half = 0; half < 2; half++) {
            int q = qbase + m0 + mt * 16 + fr + half * 8;
            float* srow = g_s + ((size_t)h * T_ + q) * T_ + kbase + n0 + 2 * kc;
            int k0 = kbase + n0 + 2 * kc;
#pragma unroll
            for (int nt = 0; nt < 8; nt++) {
                float v0 = (k0 + nt * 8 + 0 <= q) ? acc[mt][nt][half * 2 + 0] * scale : -1e30f;
                float v1 = (k0 + nt * 8 + 1 <= q) ? acc[mt][nt][half * 2 + 1] * scale : -1e30f;
                *(float2*)(srow + nt * 8) = make_float2(v0, v1);
            }
        }
}

// ---------------- attention pass B: softmax, writes PACKED probs in place ----------------
__global__ __launch_bounds__(256)
void softmax_rows() {
    int q = blockIdx.x, h = blockIdx.y;
    float* row = g_s + ((size_t)h * T_ + q) * T_;
    uint32_t* prow = (uint32_t*)row;
    int L = q + 1, pad_end = ((q >> 7) + 1) << 7, tid = threadIdx.x;
    float v[8];
    int nchunk = (L + 255) >> 8;
    float mx = -1e30f;
#pragma unroll 4
    for (int c = 0; c < nchunk; c++) {
        int i = c * 256 + tid;
        v[c] = (i < L) ? row[i] : -1e30f;
        mx = fmaxf(mx, v[c]);
    }
    mx = block_reduce_max(mx);
    float s = 0.f;
#pragma unroll 4
    for (int c = 0; c < nchunk; c++) { v[c] = __expf(v[c] - mx); s += v[c]; }
    float tot = block_reduce_sum(s);
    float inv = 1.f / tot;
#pragma unroll 4
    for (int c = 0; c < nchunk; c++) {
        int i = c * 256 + tid;
        if (i < L) prow[i] = packsplit(v[c] * inv);
    }
    for (int i = L + tid; i < pad_end; i += 256) prow[i] = 0u;
}

// ---------------- attention pass C: O = P @ V -> packed g_attnp ----------------
__global__ __launch_bounds__(256, 2)
void gemm_b16_pv() {
    int qt = (int)gridDim.x - 1 - (int)blockIdx.x;   // longest first
    int h = blockIdx.y;
    int rbase = qt * 128, kvh = h >> 2;

    B16_DECL();
    const uint32_t* Arow = (const uint32_t*)g_s + (size_t)h * T_ * T_ +
                           (size_t)(rbase + am) * T_;
    const uint32_t* Bp = g_vp + kvh * DH_;           // row stride 512
    int br0 = tid >> 5, bc4 = tid & 31;

#define LOADG(K0)                                                                    \
    do {                                                                             \
        ra0 = *(const uint4*)(Arow + (K0) + ak0);                                    \
        ra1 = *(const uint4*)(Arow + (K0) + ak0 + 4);                                \
        rb0 = *(const uint4*)(Bp + (size_t)((K0) + br0) * 512 + bc4 * 4);            \
        rb1 = *(const uint4*)(Bp + (size_t)((K0) + br0 + 8) * 512 + bc4 * 4);        \
    } while (0)

    int nk = (qt + 1) * 8;
    LOADG(0);
    B16_STORE_A_TR(0);
    B16_STORE_B_ROW(0, br0, bc4);
    __syncthreads();
    for (int kt = 0; kt < nk; kt++) {
        int cur = kt & 1;
        if (kt + 1 < nk) LOADG((kt + 1) * 16);
        B16_COMPUTE(cur);
        if (kt + 1 < nk) {
            B16_STORE_A_TR(cur ^ 1);
            B16_STORE_B_ROW(cur ^ 1, br0, bc4);
            __syncthreads();
        }
    }
#undef LOADG

#pragma unroll
    for (int mt = 0; mt < 2; mt++)
#pragma unroll
        for (int half = 0; half < 2; half++) {
            int q = rbase + m0 + mt * 16 + fr + half * 8;
            size_t base = (size_t)q * H_ + h * DH_ + n0 + 2 * kc;
#pragma unroll
            for (int nt = 0; nt < 8; nt++) {
                g_attnp[base + nt * 8] = packsplit(acc[mt][nt][half * 2 + 0]);
                g_attnp[base + nt * 8 + 1] = packsplit(acc[mt][nt][half * 2 + 1]);
            }
        }
}

// ---------------- elementwise ----------------
__global__ void embcat_kernel(const int* __restrict__ ids,
                              const float* __restrict__ emb_w,
                              const float* __restrict__ hid,
                              const float* __restrict__ we,
                              const float* __restrict__ wh) {
    int t = blockIdx.x;
    const float* er = emb_w + (size_t)ids[t] * H_;
    const float* hr = hid + (size_t)t * H_;
    uint32_t* cp = g_catp + (size_t)t * 2 * H_;
    float ss = 0.f;
    for (int h = threadIdx.x; h < H_; h += blockDim.x) { float v = er[h]; ss += v * v; }
    float rs = rsqrtf(block_reduce_sum(ss) / H_ + EPS_);
    for (int h = threadIdx.x; h < H_; h += blockDim.x)
        cp[h] = packsplit(er[h] * rs * (1.f + we[h]));
    ss = 0.f;
    for (int h = threadIdx.x; h < H_; h += blockDim.x) { float v = hr[h]; ss += v * v; }
    rs = rsqrtf(block_reduce_sum(ss) / H_ + EPS_);
    for (int h = threadIdx.x; h < H_; h += blockDim.x)
        cp[H_ + h] = packsplit(hr[h] * rs * (1.f + wh[h]));
}

__global__ void rmsnorm_kernel(const float* __restrict__ in,
                               const float* __restrict__ w,
                               float* __restrict__ outf,
                               uint32_t* __restrict__ outp) {
    int t = blockIdx.x;
    const float* r = in + (size_t)t * H_;
    float ss = 0.f;
    for (int h = threadIdx.x; h < H_; h += blockDim.x) { float v = r[h]; ss += v * v; }
    float rs = rsqrtf(block_reduce_sum(ss) / H_ + EPS_);
    for (int h = threadIdx.x; h < H_; h += blockDim.x) {
        float v = r[h] * rs * (1.f + w[h]);
        if (outf) outf[(size_t)t * H_ + h] = v;
        outp[(size_t)t * H_ + h] = packsplit(v);
    }
}

// per-head rms + rope: read fp32 g_qkv, write packed plane
__global__ void qkrope_kernel(int coloff, uint32_t* __restrict__ outp, int ostride,
                              const float* __restrict__ nw,
                              const int* __restrict__ positions) {
    int t = blockIdx.x, h = blockIdx.y;
    const float* v = g_qkv + (size_t)t * 3072 + coloff + h * DH_;
    int d = threadIdx.x;
    float val = v[d];
    float ss = val * val;
#pragma unroll
    for (int o = 16; o > 0; o >>= 1) ss += __shfl_xor_sync(0xffffffffu, ss, o);
    __shared__ float ws[4];
    if ((d & 31) == 0) ws[d >> 5] = ss;
    __syncthreads();
    float rs = rsqrtf((ws[0] + ws[1] + ws[2] + ws[3]) / DH_ + EPS_);
    float n = val * rs * (1.f + nw[d]);
    __shared__ float nv[DH_];
    nv[d] = n;
    __syncthreads();
    int pos = positions[t];
    int i = d & 63;
    float inv = expf(-((float)i / 64.f) * 13.815510557964274f);
    float ang = (float)pos * inv;
    float c = cosf(ang), s = sinf(ang);
    float outv = (d < 64) ? nv[d] * c - nv[d + 64] * s : nv[d] * c + nv[d - 64] * s;
    outp[(size_t)t * ostride + h * DH_ + d] = packsplit(outv);
}

__global__ void zero_counts_kernel() { if (threadIdx.x < E_) g_counts[threadIdx.x] = 0; }

__global__ void router_kernel(const float* __restrict__ rw) {
    int t = blockIdx.x;
    __shared__ float part[256];
    __shared__ float logits[E_];
    int tid = threadIdx.x, e = tid >> 4, c = tid & 15;
    float s = 0.f;
    const float* xr = g_xn + (size_t)t * H_;
    for (int h = c * 128; h < (c + 1) * 128; h++) s += xr[h] * rw[(size_t)h * E_ + e];
    part[tid] = s;
    __syncthreads();
    if (c == 0) {
        float tot = 0.f;
        for (int i = 0; i < 16; i++) tot += part[e * 16 + i];
        logits[e] = tot;
    }
    __syncthreads();
    if (tid == 0) {
        float mx = -1e30f;
        for (int i = 0; i < E_; i++) mx = fmaxf(mx, logits[i]);
        float p[E_];
        for (int i = 0; i < E_; i++) p[i] = expf(logits[i] - mx);
        int i0 = 0; float v0 = p[0];
        for (int i = 1; i < E_; i++) if (p[i] > v0) { v0 = p[i]; i0 = i; }
        int i1 = -1; float v1 = -1.f;
        for (int i = 0; i < E_; i++) if (i != i0 && p[i] > v1) { v1 = p[i]; i1 = i; }
        float denom = v0 + v1;
        g_top_idx[t * 2 + 0] = i0; g_top_idx[t * 2 + 1] = i1;
        g_top_w[t * 2 + 0] = v0 / denom; g_top_w[t * 2 + 1] = v1 / denom;
        atomicAdd(&g_counts[i0], 1);
        atomicAdd(&g_counts[i1], 1);
    }
}

__global__ void offsets_kernel() {
    if (threadIdx.x == 0) {
        int acc = 0;
        for (int e = 0; e < E_; e++) { g_offs[e] = acc; acc += g_counts[e]; }
        g_offs[E_] = acc;
    }
    if (threadIdx.x < E_) g_counts2[threadIdx.x] = 0;
}

__global__ void scatter_kernel() {
    int t = blockIdx.x * blockDim.x + threadIdx.x;
    if (t >= T_) return;
    for (int k = 0; k < TOPK_; k++) {
        int e = g_top_idx[t * 2 + k];
        int pos = atomicAdd(&g_counts2[e], 1);
        int slot = g_offs[e] + pos;
        g_tok_of_slot[slot] = t;
        g_gate_of_slot[slot] = g_top_w[t * 2 + k];
        g_slot_of_tok[t * 2 + k] = slot;
    }
}

__global__ void silu_mul_kernel() {
    size_t i = (size_t)blockIdx.x * blockDim.x + threadIdx.x;
    if (i >= (size_t)T_ * TOPK_ * I_) return;
    float x = g_gbuf[i];
    g_actp[i] = packsplit((x / (1.f + expf(-x))) * g_ubuf[i]);
}

__global__ void final_kernel(const float* __restrict__ fw, float* __restrict__ out) {
    int t = blockIdx.x;
    __shared__ float buf[H_];
    int s0 = g_slot_of_tok[t * 2 + 0], s1 = g_slot_of_tok[t * 2 + 1];
    float ss = 0.f;
    for (int h = threadIdx.x; h < H_; h += blockDim.x) {
        float v = g_x[(size_t)t * H_ + h] + g_downbuf[(size_t)s0 * H_ + h] +
                  g_downbuf[(size_t)s1 * H_ + h];
        buf[h] = v;
        ss += v * v;
    }
    float rs = rsqrtf(block_reduce_sum(ss) / H_ + EPS_);
    for (int h = threadIdx.x; h < H_; h += blockDim.x)
        out[(size_t)t * H_ + h] = buf[h] * rs * (1.f + fw[h]);
}

// ---------------- launch ----------------
extern "C" void kernel_launch(void* const* d_in, const int* in_sizes, int n_in,
                              void* d_out, int out_size) {
    const int* input_ids      = (const int*)d_in[0];
    const int* positions      = (const int*)d_in[1];
    const float* hidden       = (const float*)d_in[2];
    const float* embed_w      = (const float*)d_in[4];
    const float* fc_w         = (const float*)d_in[5];
    const float* pre_fc_emb_w = (const float*)d_in[6];
    const float* pre_fc_hid_w = (const float*)d_in[7];
    const float* in_ln_w      = (const float*)d_in[8];
    const float* post_ln_w    = (const float*)d_in[9];
    const float* final_norm_w = (const float*)d_in[10];
    const float* wq           = (const float*)d_in[11];
    const float* wk           = (const float*)d_in[12];
    const float* wv           = (const float*)d_in[13];
    const float* wo           = (const float*)d_in[14];
    const float* q_norm_w     = (const float*)d_in[15];
    const float* k_norm_w     = (const float*)d_in[16];
    const float* router_w     = (const float*)d_in[17];
    const float* w_gate       = (const float*)d_in[18];
    const float* w_up         = (const float*)d_in[19];
    const float* w_down       = (const float*)d_in[20];
    float* out = (float*)d_out;

    float *p_x, *p_res, *p_xn, *p_g, *p_u, *p_down, *p_gate;
    int *p_tok, *p_offs;
    uint32_t *p_catp, *p_xnp, *p_qp, *p_kp, *p_attnp, *p_actp;
    cudaGetSymbolAddress((void**)&p_x, g_x);
    cudaGetSymbolAddress((void**)&p_res, g_res);
    cudaGetSymbolAddress((void**)&p_xn, g_xn);
    cudaGetSymbolAddress((void**)&p_g, g_gbuf);
    cudaGetSymbolAddress((void**)&p_u, g_ubuf);
    cudaGetSymbolAddress((void**)&p_down, g_downbuf);
    cudaGetSymbolAddress((void**)&p_gate, g_gate_of_slot);
    cudaGetSymbolAddress((void**)&p_tok, g_tok_of_slot);
    cudaGetSymbolAddress((void**)&p_offs, g_offs);
    cudaGetSymbolAddress((void**)&p_catp, g_catp);
    cudaGetSymbolAddress((void**)&p_xnp, g_xnp);
    cudaGetSymbolAddress((void**)&p_qp, g_qp);
    cudaGetSymbolAddress((void**)&p_kp, g_kp);
    cudaGetSymbolAddress((void**)&p_attnp, g_attnp);
    cudaGetSymbolAddress((void**)&p_actp, g_actp);

    // 1. embed + rms -> packed cat
    embcat_kernel<<<T_, 256>>>(input_ids, embed_w, hidden, pre_fc_emb_w, pre_fc_hid_w);

    // 2. fc: x = cat @ fc_w ; residual = x (weights split at staging)
    gemm_b16<<<dim3(H_ / 128, T_ / 128), 256>>>(p_catp, fc_w, p_x,
                                                T_, 2 * H_, 2 * H_, H_, H_,
                                                nullptr, nullptr, p_res, nullptr, 0, nullptr);

    // 3. in_ln -> packed
    rmsnorm_kernel<<<T_, 256>>>(p_x, in_ln_w, nullptr, p_xnp);

    // 4. fused qkv: q,k fp32 -> g_qkv ; v packed -> g_vp
    gemm_b16_qkv<<<dim3(24, T_ / 128), 256>>>(p_xnp, wq, wk, wv);

    // 5. q/k norm + rope -> packed planes
    qkrope_kernel<<<dim3(T_, NH_), DH_>>>(0, p_qp, NH_ * DH_, q_norm_w, positions);
    qkrope_kernel<<<dim3(T_, NKV_), DH_>>>(2048, p_kp, NKV_ * DH_, k_norm_w, positions);

    // 6. attention: QK^T -> softmax(pack) -> PV
    gemm_b16_qk<<<dim3(T_ / 128, T_ / 128, NH_), 256>>>();
    softmax_rows<<<dim3(T_, NH_), 256>>>();
    gemm_b16_pv<<<dim3(T_ / 128, NH_), 256>>>();

    // 7. wo + residual -> x
    gemm_b16<<<dim3(H_ / 128, T_ / 128), 256>>>(p_attnp, wo, p_x,
                                                T_, NH_ * DH_, NH_ * DH_, H_, H_,
                                                nullptr, p_res, nullptr, nullptr, 0, nullptr);

    // 8. post_ln -> fp32 (router) + packed (MoE)
    rmsnorm_kernel<<<T_, 256>>>(p_x, post_ln_w, p_xn, p_xnp);

    // 9. router + bucketing
    zero_counts_kernel<<<1, 32>>>();
    router_kernel<<<T_, 256>>>(router_w);
    offsets_kernel<<<1, 32>>>();
    scatter_kernel<<<(T_ + 255) / 256, 256>>>();

    // 10. MoE grouped GEMMs
    gemm_b16<<<dim3(I_ / 128, T_ / 128, E_), 256>>>(p_xnp, w_gate, p_g,
                                                    0, H_, H_, I_, I_,
                                                    p_tok, nullptr, nullptr, p_offs,
                                                    (long long)H_ * I_, nullptr);
    gemm_b16<<<dim3(I_ / 128, T_ / 128, E_), 256>>>(p_xnp, w_up, p_u,
                                                    0, H_, H_, I_, I_,
                                                    p_tok, nullptr, nullptr, p_offs,
                                                    (long long)H_ * I_, nullptr);
    silu_mul_kernel<<<((size_t)T_ * TOPK_ * I_ + 255) / 256, 256>>>();
    gemm_b16<<<dim3(H_ / 128, T_ / 128, E_), 256>>>(p_actp, w_down, p_down,
                                                    0, I_, I_, H_, H_,
                                                    nullptr, nullptr, nullptr, p_offs,
                                                    (long long)I_ * H_, p_gate);

    // 11. combine + final rms
    final_kernel<<<T_, 256>>>(final_norm_w, out);
}

// round 17
// speedup vs baseline: 1.8950x; 1.0699x over previous
#include <cuda_runtime.h>
#include <cuda_bf16.h>
#include <math.h>
#include <stdint.h>

#define T_ 2048
#define H_ 2048
#define NH_ 16
#define NKV_ 4
#define DH_ 128
#define E_ 16
#define TOPK_ 2
#define I_ 1024
#define EPS_ 1e-6f

// ---------------- fp32 scratch ----------------
__device__ float g_x[(size_t)T_ * H_];
__device__ float g_res[(size_t)T_ * H_];
__device__ float g_xn[(size_t)T_ * H_];
__device__ float g_qkv[(size_t)T_ * 3072];
__device__ float g_s[(size_t)NH_ * T_ * T_];
__device__ float g_gbuf[(size_t)T_ * TOPK_ * I_];
__device__ float g_ubuf[(size_t)T_ * TOPK_ * I_];
__device__ float g_downbuf[(size_t)T_ * TOPK_ * H_];
__device__ int   g_top_idx[T_ * TOPK_];
__device__ float g_top_w[T_ * TOPK_];
__device__ int   g_counts[E_];
__device__ int   g_counts2[E_];
__device__ int   g_offs[E_ + 1];
__device__ int   g_tok_of_slot[T_ * TOPK_];
__device__ float g_gate_of_slot[T_ * TOPK_];
__device__ int   g_slot_of_tok[T_ * TOPK_];

// ---------------- packed (hi,lo) bf16 activation planes ----------------
__device__ uint32_t g_catp[(size_t)T_ * 2 * H_];
__device__ uint32_t g_xnp[(size_t)T_ * H_];
__device__ uint32_t g_qp[(size_t)T_ * NH_ * DH_];
__device__ uint32_t g_kp[(size_t)T_ * NKV_ * DH_];
__device__ uint32_t g_vp[(size_t)T_ * NKV_ * DH_];
__device__ uint32_t g_attnp[(size_t)T_ * H_];
__device__ uint32_t g_actp[(size_t)T_ * TOPK_ * I_];

// ---------------- helpers ----------------
__device__ __forceinline__ float block_reduce_sum(float v) {
    __shared__ float sb[33];
    int tid = threadIdx.x;
#pragma unroll
    for (int o = 16; o > 0; o >>= 1) v += __shfl_xor_sync(0xffffffffu, v, o);
    if ((tid & 31) == 0) sb[tid >> 5] = v;
    __syncthreads();
    if (tid == 0) {
        float s = 0.f;
        int nw = (blockDim.x + 31) >> 5;
        for (int i = 0; i < nw; i++) s += sb[i];
        sb[32] = s;
    }
    __syncthreads();
    return sb[32];
}
__device__ __forceinline__ float block_reduce_max(float v) {
    __shared__ float sb[33];
    int tid = threadIdx.x;
#pragma unroll
    for (int o = 16; o > 0; o >>= 1) v = fmaxf(v, __shfl_xor_sync(0xffffffffu, v, o));
    if ((tid & 31) == 0) sb[tid >> 5] = v;
    __syncthreads();
    if (tid == 0) {
        float s = -1e30f;
        int nw = (blockDim.x + 31) >> 5;
        for (int i = 0; i < nw; i++) s = fmaxf(s, sb[i]);
        sb[32] = s;
    }
    __syncthreads();
    return sb[32];
}

__device__ __forceinline__ uint32_t packsplit(float x) {
    __nv_bfloat16 h = __float2bfloat16_rn(x);
    float hf = __bfloat162float(h);
    __nv_bfloat16 l = __float2bfloat16_rn(x - hf);
    return (uint32_t)__bfloat16_as_ushort(h) |
           ((uint32_t)__bfloat16_as_ushort(l) << 16);
}
__device__ __forceinline__ void mma_bf16(float* d, const uint32_t* a, const uint32_t* b) {
    asm volatile("mma.sync.aligned.m16n8k16.row.col.f32.bf16.bf16.f32 "
                 "{%0,%1,%2,%3}, {%4,%5,%6,%7}, {%8,%9}, {%0,%1,%2,%3};"
                 : "+f"(d[0]), "+f"(d[1]), "+f"(d[2]), "+f"(d[3])
                 : "r"(a[0]), "r"(a[1]), "r"(a[2]), "r"(a[3]), "r"(b[0]), "r"(b[1]));
}

#define TPW 136  // word pitch; kc*8+fr spans 32 banks -> conflict-free fragment loads

// smem: 4 planes (Ah,Al,Bh,Bl), each 8 k-pair rows x TPW, pre-paired (hi,hi)/(lo,lo)
#define B16_DECL()                                                                   \
    __shared__ uint32_t Ahs[2][8 * TPW], Als[2][8 * TPW];                            \
    __shared__ uint32_t Bhs[2][8 * TPW], Bls[2][8 * TPW];                            \
    int tid = threadIdx.x, lane = tid & 31, wid = tid >> 5;                          \
    int m0 = (wid & 3) * 32, n0 = (wid >> 2) * 64;                                   \
    int fr = lane >> 2, kc = lane & 3;                                               \
    int am = tid & 127, ak0 = (tid >> 7) * 8;                                        \
    float acc[2][8][4];                                                              \
    _Pragma("unroll") for (int i_ = 0; i_ < 2; i_++)                                 \
        _Pragma("unroll") for (int j_ = 0; j_ < 8; j_++)                             \
            _Pragma("unroll") for (int c_ = 0; c_ < 4; c_++) acc[i_][j_][c_] = 0.f;  \
    uint4 ra0, ra1, rb0, rb1;                                                        \
    float4 fb0, fb1;                                                                 \
    const uint4 Z4 = make_uint4(0, 0, 0, 0);                                         \
    (void)Z4; (void)rb0; (void)rb1; (void)fb0; (void)fb1;

// A: packed words (8 consecutive k at fixed m) -> pair locally, store to Ah/Al
#define B16_STORE_A_TR(BUF)                                                          \
    do {                                                                             \
        uint32_t v_[8] = {ra0.x, ra0.y, ra0.z, ra0.w, ra1.x, ra1.y, ra1.z, ra1.w};   \
        _Pragma("unroll")                                                            \
        for (int j_ = 0; j_ < 4; j_++) {                                             \
            int kp_ = (ak0 >> 1) + j_;                                               \
            Ahs[BUF][kp_ * TPW + am] = __byte_perm(v_[2 * j_], v_[2 * j_ + 1], 0x5410);\
            Als[BUF][kp_ * TPW + am] = __byte_perm(v_[2 * j_], v_[2 * j_ + 1], 0x7632);\
        }                                                                            \
    } while (0)

// B transposed (qk): packed words, same op into Bh/Bl
#define B16_STORE_B_TR(BUF)                                                          \
    do {                                                                             \
        uint32_t v_[8] = {rb0.x, rb0.y, rb0.z, rb0.w, rb1.x, rb1.y, rb1.z, rb1.w};   \
        _Pragma("unroll")                                                            \
        for (int j_ = 0; j_ < 4; j_++) {                                             \
            int kp_ = (ak0 >> 1) + j_;                                               \
            Bhs[BUF][kp_ * TPW + am] = __byte_perm(v_[2 * j_], v_[2 * j_ + 1], 0x5410);\
            Bls[BUF][kp_ * TPW + am] = __byte_perm(v_[2 * j_], v_[2 * j_ + 1], 0x7632);\
        }                                                                            \
    } while (0)

// B packed row pair (pv): rb0 = k row 2*BR0, rb1 = k row 2*BR0+1 (4 n each)
#define B16_STORE_B_ROWP(BUF, BR0, BC4)                                              \
    do {                                                                             \
        uint4 h_ = make_uint4(__byte_perm(rb0.x, rb1.x, 0x5410),                     \
                              __byte_perm(rb0.y, rb1.y, 0x5410),                     \
                              __byte_perm(rb0.z, rb1.z, 0x5410),                     \
                              __byte_perm(rb0.w, rb1.w, 0x5410));                    \
        uint4 l_ = make_uint4(__byte_perm(rb0.x, rb1.x, 0x7632),                     \
                              __byte_perm(rb0.y, rb1.y, 0x7632),                     \
                              __byte_perm(rb0.z, rb1.z, 0x7632),                     \
                              __byte_perm(rb0.w, rb1.w, 0x7632));                    \
        *(uint4*)&Bhs[BUF][(BR0) * TPW + (BC4) * 4] = h_;                            \
        *(uint4*)&Bls[BUF][(BR0) * TPW + (BC4) * 4] = l_;                            \
    } while (0)

// B fp32 row pair (weights): fb0 = k row 2*BR0, fb1 = k row 2*BR0+1
#define B16_STORE_B_ROWF(BUF, BR0, BC4)                                              \
    do {                                                                             \
        uint32_t q0_ = packsplit(fb0.x), q1_ = packsplit(fb1.x);                     \
        uint32_t q2_ = packsplit(fb0.y), q3_ = packsplit(fb1.y);                     \
        uint32_t q4_ = packsplit(fb0.z), q5_ = packsplit(fb1.z);                     \
        uint32_t q6_ = packsplit(fb0.w), q7_ = packsplit(fb1.w);                     \
        uint4 h_ = make_uint4(__byte_perm(q0_, q1_, 0x5410),                         \
                              __byte_perm(q2_, q3_, 0x5410),                         \
                              __byte_perm(q4_, q5_, 0x5410),                         \
                              __byte_perm(q6_, q7_, 0x5410));                        \
        uint4 l_ = make_uint4(__byte_perm(q0_, q1_, 0x7632),                         \
                              __byte_perm(q2_, q3_, 0x7632),                         \
                              __byte_perm(q4_, q5_, 0x7632),                         \
                              __byte_perm(q6_, q7_, 0x7632));                        \
        *(uint4*)&Bhs[BUF][(BR0) * TPW + (BC4) * 4] = h_;                            \
        *(uint4*)&Bls[BUF][(BR0) * TPW + (BC4) * 4] = l_;                            \
    } while (0)

#define B16_COMPUTE(CUR)                                                             \
    do {                                                                             \
        const uint32_t* Ah_ = &Ahs[CUR][0];                                          \
        const uint32_t* Al_ = &Als[CUR][0];                                          \
        const uint32_t* Bh_ = &Bhs[CUR][0];                                          \
        const uint32_t* Bl_ = &Bls[CUR][0];                                          \
        int rlo = kc * TPW, rhi = (kc + 4) * TPW;                                    \
        uint32_t ah[2][4], al[2][4];                                                 \
        _Pragma("unroll")                                                            \
        for (int mt = 0; mt < 2; mt++) {                                             \
            int mm = m0 + mt * 16 + fr;                                              \
            ah[mt][0] = Ah_[rlo + mm];     ah[mt][1] = Ah_[rlo + mm + 8];            \
            ah[mt][2] = Ah_[rhi + mm];     ah[mt][3] = Ah_[rhi + mm + 8];            \
            al[mt][0] = Al_[rlo + mm];     al[mt][1] = Al_[rlo + mm + 8];            \
            al[mt][2] = Al_[rhi + mm];     al[mt][3] = Al_[rhi + mm + 8];            \
        }                                                                            \
        _Pragma("unroll")                                                            \
        for (int nt = 0; nt < 8; nt++) {                                             \
            int nn = n0 + nt * 8 + fr;                                               \
            uint32_t bh[2] = {Bh_[rlo + nn], Bh_[rhi + nn]};                         \
            uint32_t bl[2] = {Bl_[rlo + nn], Bl_[rhi + nn]};                         \
            _Pragma("unroll")                                                        \
            for (int mt = 0; mt < 2; mt++) {                                         \
                mma_bf16(acc[mt][nt], ah[mt], bh);                                   \
                mma_bf16(acc[mt][nt], ah[mt], bl);                                   \
                mma_bf16(acc[mt][nt], al[mt], bh);                                   \
            }                                                                        \
        }                                                                            \
    } while (0)

// ---------------- split-bf16 GEMM (A packed gather, B fp32 weights) ----------------
__global__ __launch_bounds__(256, 2)
void gemm_b16(const uint32_t* __restrict__ A, const float* __restrict__ B,
              float* __restrict__ C,
              int M, int Kd, int lda, int ldb, int ldc,
              const int* __restrict__ rowmap,
              const float* __restrict__ addsrc, float* __restrict__ Cdup,
              const int* __restrict__ segoff, long long strideB,
              const float* __restrict__ rowscale) {
    int row0 = 0, rowEnd = M;
    const float* Bp = B;
    if (segoff) {
        int e = blockIdx.z;
        row0 = segoff[e];
        rowEnd = segoff[e + 1];
        Bp = B + (long long)e * strideB;
    }
    int rbase = row0 + blockIdx.y * 128;
    if (rbase >= rowEnd) return;
    int cbase = blockIdx.x * 128;

    B16_DECL();
    const uint32_t* Arow = nullptr;
    if (rbase + am < rowEnd) {
        int m = rowmap ? rowmap[rbase + am] : rbase + am;
        Arow = A + (long long)m * lda;
    }
    const float* Brow_ = Bp + cbase;
    int br0 = tid >> 5, bc4 = tid & 31;

#define LOADG(K0)                                                                    \
    do {                                                                             \
        if (Arow) {                                                                  \
            ra0 = *(const uint4*)(Arow + (K0) + ak0);                                \
            ra1 = *(const uint4*)(Arow + (K0) + ak0 + 4);                            \
        } else { ra0 = Z4; ra1 = Z4; }                                               \
        fb0 = *(const float4*)(Brow_ + (long long)((K0) + 2 * br0) * ldb + bc4 * 4); \
        fb1 = *(const float4*)(Brow_ + (long long)((K0) + 2 * br0 + 1) * ldb + bc4 * 4);\
    } while (0)

    int nk = Kd >> 4;
    LOADG(0);
    B16_STORE_A_TR(0);
    B16_STORE_B_ROWF(0, br0, bc4);
    __syncthreads();
    for (int kt = 0; kt < nk; kt++) {
        int cur = kt & 1;
        if (kt + 1 < nk) LOADG((kt + 1) * 16);
        B16_COMPUTE(cur);
        if (kt + 1 < nk) {
            B16_STORE_A_TR(cur ^ 1);
            B16_STORE_B_ROWF(cur ^ 1, br0, bc4);
            __syncthreads();
        }
    }
#undef LOADG

#pragma unroll
    for (int mt = 0; mt < 2; mt++)
#pragma unroll
        for (int half = 0; half < 2; half++) {
            int row = rbase + m0 + mt * 16 + fr + half * 8;
            if (row >= rowEnd) continue;
            float sc = rowscale ? rowscale[row] : 1.f;
            long long base = (long long)row * ldc + cbase + n0 + 2 * kc;
#pragma unroll
            for (int nt = 0; nt < 8; nt++) {
                long long o = base + nt * 8;
                float2 v = make_float2(acc[mt][nt][half * 2 + 0] * sc,
                                       acc[mt][nt][half * 2 + 1] * sc);
                if (addsrc) {
                    float2 s = *(const float2*)(addsrc + o);
                    v.x += s.x; v.y += s.y;
                }
                *(float2*)(C + o) = v;
                if (Cdup) *(float2*)(Cdup + o) = v;
            }
        }
}

// fused QKV: q,k -> fp32 g_qkv; v -> packed g_vp
__global__ __launch_bounds__(256, 2)
void gemm_b16_qkv(const uint32_t* __restrict__ A,
                  const float* __restrict__ wq, const float* __restrict__ wk,
                  const float* __restrict__ wv) {
    int x = blockIdx.x;
    const float* Bsel;
    int ldb, bcol;
    if (x < 16)      { Bsel = wq; ldb = 2048; bcol = x * 128; }
    else if (x < 20) { Bsel = wk; ldb = 512;  bcol = (x - 16) * 128; }
    else             { Bsel = wv; ldb = 512;  bcol = (x - 20) * 128; }
    int rbase = blockIdx.y * 128;

    B16_DECL();
    const uint32_t* Arow = A + (long long)(rbase + am) * H_;
    const float* Brow_ = Bsel + bcol;
    int br0 = tid >> 5, bc4 = tid & 31;

#define LOADG(K0)                                                                    \
    do {                                                                             \
        ra0 = *(const uint4*)(Arow + (K0) + ak0);                                    \
        ra1 = *(const uint4*)(Arow + (K0) + ak0 + 4);                                \
        fb0 = *(const float4*)(Brow_ + (long long)((K0) + 2 * br0) * ldb + bc4 * 4); \
        fb1 = *(const float4*)(Brow_ + (long long)((K0) + 2 * br0 + 1) * ldb + bc4 * 4);\
    } while (0)

    int nk = H_ >> 4;
    LOADG(0);
    B16_STORE_A_TR(0);
    B16_STORE_B_ROWF(0, br0, bc4);
    __syncthreads();
    for (int kt = 0; kt < nk; kt++) {
        int cur = kt & 1;
        if (kt + 1 < nk) LOADG((kt + 1) * 16);
        B16_COMPUTE(cur);
        if (kt + 1 < nk) {
            B16_STORE_A_TR(cur ^ 1);
            B16_STORE_B_ROWF(cur ^ 1, br0, bc4);
            __syncthreads();
        }
    }
#undef LOADG

#pragma unroll
    for (int mt = 0; mt < 2; mt++)
#pragma unroll
        for (int half = 0; half < 2; half++) {
            int row = rbase + m0 + mt * 16 + fr + half * 8;
            int col = n0 + 2 * kc;
#pragma unroll
            for (int nt = 0; nt < 8; nt++) {
                float v0 = acc[mt][nt][half * 2 + 0];
                float v1 = acc[mt][nt][half * 2 + 1];
                if (x < 20) {
                    long long o = (long long)row * 3072 + x * 128 + col + nt * 8;
                    *(float2*)(g_qkv + o) = make_float2(v0, v1);
                } else {
                    long long o = (long long)row * 512 + (x - 20) * 128 + col + nt * 8;
                    g_vp[o] = packsplit(v0);
                    g_vp[o + 1] = packsplit(v1);
                }
            }
        }
}

// ---------------- attention pass A: S = scale*Q@K^T (packed q/k), causal tiles ----------------
__global__ __launch_bounds__(256, 2)
void gemm_b16_qk() {
    int ktile = blockIdx.x, qtile = blockIdx.y, h = blockIdx.z;
    if (ktile > qtile) return;
    int qbase = qtile * 128, kbase = ktile * 128, kvh = h >> 2;

    B16_DECL();
    const uint32_t* Arow = g_qp + (size_t)(qbase + am) * 2048 + h * DH_;
    const uint32_t* Brow = g_kp + (size_t)(kbase + am) * 512 + kvh * DH_;

#define LOADG(K0)                                                                    \
    do {                                                                             \
        ra0 = *(const uint4*)(Arow + (K0) + ak0);                                    \
        ra1 = *(const uint4*)(Arow + (K0) + ak0 + 4);                                \
        rb0 = *(const uint4*)(Brow + (K0) + ak0);                                    \
        rb1 = *(const uint4*)(Brow + (K0) + ak0 + 4);                                \
    } while (0)

    const int nk = DH_ >> 4;   // 8
    LOADG(0);
    B16_STORE_A_TR(0);
    B16_STORE_B_TR(0);
    __syncthreads();
    for (int kt = 0; kt < nk; kt++) {
        int cur = kt & 1;
        if (kt + 1 < nk) LOADG((kt + 1) * 16);
        B16_COMPUTE(cur);
        if (kt + 1 < nk) {
            B16_STORE_A_TR(cur ^ 1);
            B16_STORE_B_TR(cur ^ 1);
            __syncthreads();
        }
    }
#undef LOADG

    const float scale = 0.08838834764831845f;
#pragma unroll
    for (int mt = 0; mt < 2; mt++)
#pragma unroll
        for (int half = 0; half < 2; half++) {
            int q = qbase + m0 + mt * 16 + fr + half * 8;
            float* srow = g_s + ((size_t)h * T_ + q) * T_ + kbase + n0 + 2 * kc;
            int k0 = kbase + n0 + 2 * kc;
#pragma unroll
            for (int nt = 0; nt < 8; nt++) {
                float v0 = (k0 + nt * 8 + 0 <= q) ? acc[mt][nt][half * 2 + 0] * scale : -1e30f;
                float v1 = (k0 + nt * 8 + 1 <= q) ? acc[mt][nt][half * 2 + 1] * scale : -1e30f;
                *(float2*)(srow + nt * 8) = make_float2(v0, v1);
            }
        }
}

// ---------------- attention pass B: softmax, writes PACKED probs in place ----------------
__global__ __launch_bounds__(256)
void softmax_rows() {
    int q = blockIdx.x, h = blockIdx.y;
    float* row = g_s + ((size_t)h * T_ + q) * T_;
    uint32_t* prow = (uint32_t*)row;
    int L = q + 1, pad_end = ((q >> 7) + 1) << 7, tid = threadIdx.x;
    float v[8];
    int nchunk = (L + 255) >> 8;
    float mx = -1e30f;
#pragma unroll 4
    for (int c = 0; c < nchunk; c++) {
        int i = c * 256 + tid;
        v[c] = (i < L) ? row[i] : -1e30f;
        mx = fmaxf(mx, v[c]);
    }
    mx = block_reduce_max(mx);
    float s = 0.f;
#pragma unroll 4
    for (int c = 0; c < nchunk; c++) { v[c] = __expf(v[c] - mx); s += v[c]; }
    float tot = block_reduce_sum(s);
    float inv = 1.f / tot;
#pragma unroll 4
    for (int c = 0; c < nchunk; c++) {
        int i = c * 256 + tid;
        if (i < L) prow[i] = packsplit(v[c] * inv);
    }
    for (int i = L + tid; i < pad_end; i += 256) prow[i] = 0u;
}

// ---------------- attention pass C: O = P @ V -> packed g_attnp ----------------
__global__ __launch_bounds__(256, 2)
void gemm_b16_pv() {
    int qt = (int)gridDim.x - 1 - (int)blockIdx.x;   // longest first
    int h = blockIdx.y;
    int rbase = qt * 128, kvh = h >> 2;

    B16_DECL();
    const uint32_t* Arow = (const uint32_t*)g_s + (size_t)h * T_ * T_ +
                           (size_t)(rbase + am) * T_;
    const uint32_t* Bp = g_vp + kvh * DH_;           // row stride 512
    int br0 = tid >> 5, bc4 = tid & 31;

#define LOADG(K0)                                                                    \
    do {                                                                             \
        ra0 = *(const uint4*)(Arow + (K0) + ak0);                                    \
        ra1 = *(const uint4*)(Arow + (K0) + ak0 + 4);                                \
        rb0 = *(const uint4*)(Bp + (size_t)((K0) + 2 * br0) * 512 + bc4 * 4);        \
        rb1 = *(const uint4*)(Bp + (size_t)((K0) + 2 * br0 + 1) * 512 + bc4 * 4);    \
    } while (0)

    int nk = (qt + 1) * 8;
    LOADG(0);
    B16_STORE_A_TR(0);
    B16_STORE_B_ROWP(0, br0, bc4);
    __syncthreads();
    for (int kt = 0; kt < nk; kt++) {
        int cur = kt & 1;
        if (kt + 1 < nk) LOADG((kt + 1) * 16);
        B16_COMPUTE(cur);
        if (kt + 1 < nk) {
            B16_STORE_A_TR(cur ^ 1);
            B16_STORE_B_ROWP(cur ^ 1, br0, bc4);
            __syncthreads();
        }
    }
#undef LOADG

#pragma unroll
    for (int mt = 0; mt < 2; mt++)
#pragma unroll
        for (int half = 0; half < 2; half++) {
            int q = rbase + m0 + mt * 16 + fr + half * 8;
            size_t base = (size_t)q * H_ + h * DH_ + n0 + 2 * kc;
#pragma unroll
            for (int nt = 0; nt < 8; nt++) {
                g_attnp[base + nt * 8] = packsplit(acc[mt][nt][half * 2 + 0]);
                g_attnp[base + nt * 8 + 1] = packsplit(acc[mt][nt][half * 2 + 1]);
            }
        }
}

// ---------------- elementwise ----------------
__global__ void embcat_kernel(const int* __restrict__ ids,
                              const float* __restrict__ emb_w,
                              const float* __restrict__ hid,
                              const float* __restrict__ we,
                              const float* __restrict__ wh) {
    int t = blockIdx.x;
    const float* er = emb_w + (size_t)ids[t] * H_;
    const float* hr = hid + (size_t)t * H_;
    uint32_t* cp = g_catp + (size_t)t * 2 * H_;
    float ss = 0.f;
    for (int h = threadIdx.x; h < H_; h += blockDim.x) { float v = er[h]; ss += v * v; }
    float rs = rsqrtf(block_reduce_sum(ss) / H_ + EPS_);
    for (int h = threadIdx.x; h < H_; h += blockDim.x)
        cp[h] = packsplit(er[h] * rs * (1.f + we[h]));
    ss = 0.f;
    for (int h = threadIdx.x; h < H_; h += blockDim.x) { float v = hr[h]; ss += v * v; }
    rs = rsqrtf(block_reduce_sum(ss) / H_ + EPS_);
    for (int h = threadIdx.x; h < H_; h += blockDim.x)
        cp[H_ + h] = packsplit(hr[h] * rs * (1.f + wh[h]));
}

__global__ void rmsnorm_kernel(const float* __restrict__ in,
                               const float* __restrict__ w,
                               float* __restrict__ outf,
                               uint32_t* __restrict__ outp) {
    int t = blockIdx.x;
    const float* r = in + (size_t)t * H_;
    float ss = 0.f;
    for (int h = threadIdx.x; h < H_; h += blockDim.x) { float v = r[h]; ss += v * v; }
    float rs = rsqrtf(block_reduce_sum(ss) / H_ + EPS_);
    for (int h = threadIdx.x; h < H_; h += blockDim.x) {
        float v = r[h] * rs * (1.f + w[h]);
        if (outf) outf[(size_t)t * H_ + h] = v;
        outp[(size_t)t * H_ + h] = packsplit(v);
    }
}

__global__ void qkrope_kernel(int coloff, uint32_t* __restrict__ outp, int ostride,
                              const float* __restrict__ nw,
                              const int* __restrict__ positions) {
    int t = blockIdx.x, h = blockIdx.y;
    const float* v = g_qkv + (size_t)t * 3072 + coloff + h * DH_;
    int d = threadIdx.x;
    float val = v[d];
    float ss = val * val;
#pragma unroll
    for (int o = 16; o > 0; o >>= 1) ss += __shfl_xor_sync(0xffffffffu, ss, o);
    __shared__ float ws[4];
    if ((d & 31) == 0) ws[d >> 5] = ss;
    __syncthreads();
    float rs = rsqrtf((ws[0] + ws[1] + ws[2] + ws[3]) / DH_ + EPS_);
    float n = val * rs * (1.f + nw[d]);
    __shared__ float nv[DH_];
    nv[d] = n;
    __syncthreads();
    int pos = positions[t];
    int i = d & 63;
    float inv = expf(-((float)i / 64.f) * 13.815510557964274f);
    float ang = (float)pos * inv;
    float c = cosf(ang), s = sinf(ang);
    float outv = (d < 64) ? nv[d] * c - nv[d + 64] * s : nv[d] * c + nv[d - 64] * s;
    outp[(size_t)t * ostride + h * DH_ + d] = packsplit(outv);
}

__global__ void zero_counts_kernel() { if (threadIdx.x < E_) g_counts[threadIdx.x] = 0; }

__global__ void router_kernel(const float* __restrict__ rw) {
    int t = blockIdx.x;
    __shared__ float part[256];
    __shared__ float logits[E_];
    int tid = threadIdx.x, e = tid >> 4, c = tid & 15;
    float s = 0.f;
    const float* xr = g_xn + (size_t)t * H_;
    for (int h = c * 128; h < (c + 1) * 128; h++) s += xr[h] * rw[(size_t)h * E_ + e];
    part[tid] = s;
    __syncthreads();
    if (c == 0) {
        float tot = 0.f;
        for (int i = 0; i < 16; i++) tot += part[e * 16 + i];
        logits[e] = tot;
    }
    __syncthreads();
    if (tid == 0) {
        float mx = -1e30f;
        for (int i = 0; i < E_; i++) mx = fmaxf(mx, logits[i]);
        float p[E_];
        for (int i = 0; i < E_; i++) p[i] = expf(logits[i] - mx);
        int i0 = 0; float v0 = p[0];
        for (int i = 1; i < E_; i++) if (p[i] > v0) { v0 = p[i]; i0 = i; }
        int i1 = -1; float v1 = -1.f;
        for (int i = 0; i < E_; i++) if (i != i0 && p[i] > v1) { v1 = p[i]; i1 = i; }
        float denom = v0 + v1;
        g_top_idx[t * 2 + 0] = i0; g_top_idx[t * 2 + 1] = i1;
        g_top_w[t * 2 + 0] = v0 / denom; g_top_w[t * 2 + 1] = v1 / denom;
        atomicAdd(&g_counts[i0], 1);
        atomicAdd(&g_counts[i1], 1);
    }
}

__global__ void offsets_kernel() {
    if (threadIdx.x == 0) {
        int acc = 0;
        for (int e = 0; e < E_; e++) { g_offs[e] = acc; acc += g_counts[e]; }
        g_offs[E_] = acc;
    }
    if (threadIdx.x < E_) g_counts2[threadIdx.x] = 0;
}

__global__ void scatter_kernel() {
    int t = blockIdx.x * blockDim.x + threadIdx.x;
    if (t >= T_) return;
    for (int k = 0; k < TOPK_; k++) {
        int e = g_top_idx[t * 2 + k];
        int pos = atomicAdd(&g_counts2[e], 1);
        int slot = g_offs[e] + pos;
        g_tok_of_slot[slot] = t;
        g_gate_of_slot[slot] = g_top_w[t * 2 + k];
        g_slot_of_tok[t * 2 + k] = slot;
    }
}

__global__ void silu_mul_kernel() {
    size_t i = (size_t)blockIdx.x * blockDim.x + threadIdx.x;
    if (i >= (size_t)T_ * TOPK_ * I_) return;
    float x = g_gbuf[i];
    g_actp[i] = packsplit((x / (1.f + expf(-x))) * g_ubuf[i]);
}

__global__ void final_kernel(const float* __restrict__ fw, float* __restrict__ out) {
    int t = blockIdx.x;
    __shared__ float buf[H_];
    int s0 = g_slot_of_tok[t * 2 + 0], s1 = g_slot_of_tok[t * 2 + 1];
    float ss = 0.f;
    for (int h = threadIdx.x; h < H_; h += blockDim.x) {
        float v = g_x[(size_t)t * H_ + h] + g_downbuf[(size_t)s0 * H_ + h] +
                  g_downbuf[(size_t)s1 * H_ + h];
        buf[h] = v;
        ss += v * v;
    }
    float rs = rsqrtf(block_reduce_sum(ss) / H_ + EPS_);
    for (int h = threadIdx.x; h < H_; h += blockDim.x)
        out[(size_t)t * H_ + h] = buf[h] * rs * (1.f + fw[h]);
}

// ---------------- launch ----------------
extern "C" void kernel_launch(void* const* d_in, const int* in_sizes, int n_in,
                              void* d_out, int out_size) {
    const int* input_ids      = (const int*)d_in[0];
    const int* positions      = (const int*)d_in[1];
    const float* hidden       = (const float*)d_in[2];
    const float* embed_w      = (const float*)d_in[4];
    const float* fc_w         = (const float*)d_in[5];
    const float* pre_fc_emb_w = (const float*)d_in[6];
    const float* pre_fc_hid_w = (const float*)d_in[7];
    const float* in_ln_w      = (const float*)d_in[8];
    const float* post_ln_w    = (const float*)d_in[9];
    const float* final_norm_w = (const float*)d_in[10];
    const float* wq           = (const float*)d_in[11];
    const float* wk           = (const float*)d_in[12];
    const float* wv           = (const float*)d_in[13];
    const float* wo           = (const float*)d_in[14];
    const float* q_norm_w     = (const float*)d_in[15];
    const float* k_norm_w     = (const float*)d_in[16];
    const float* router_w     = (const float*)d_in[17];
    const float* w_gate       = (const float*)d_in[18];
    const float* w_up         = (const float*)d_in[19];
    const float* w_down       = (const float*)d_in[20];
    float* out = (float*)d_out;

    float *p_x, *p_res, *p_xn, *p_g, *p_u, *p_down, *p_gate;
    int *p_tok, *p_offs;
    uint32_t *p_catp, *p_xnp, *p_qp, *p_kp, *p_attnp, *p_actp;
    cudaGetSymbolAddress((void**)&p_x, g_x);
    cudaGetSymbolAddress((void**)&p_res, g_res);
    cudaGetSymbolAddress((void**)&p_xn, g_xn);
    cudaGetSymbolAddress((void**)&p_g, g_gbuf);
    cudaGetSymbolAddress((void**)&p_u, g_ubuf);
    cudaGetSymbolAddress((void**)&p_down, g_downbuf);
    cudaGetSymbolAddress((void**)&p_gate, g_gate_of_slot);
    cudaGetSymbolAddress((void**)&p_tok, g_tok_of_slot);
    cudaGetSymbolAddress((void**)&p_offs, g_offs);
    cudaGetSymbolAddress((void**)&p_catp, g_catp);
    cudaGetSymbolAddress((void**)&p_xnp, g_xnp);
    cudaGetSymbolAddress((void**)&p_qp, g_qp);
    cudaGetSymbolAddress((void**)&p_kp, g_kp);
    cudaGetSymbolAddress((void**)&p_attnp, g_attnp);
    cudaGetSymbolAddress((void**)&p_actp, g_actp);

    // 1. embed + rms -> packed cat
    embcat_kernel<<<T_, 256>>>(input_ids, embed_w, hidden, pre_fc_emb_w, pre_fc_hid_w);

    // 2. fc: x = cat @ fc_w ; residual = x
    gemm_b16<<<dim3(H_ / 128, T_ / 128), 256>>>(p_catp, fc_w, p_x,
                                                T_, 2 * H_, 2 * H_, H_, H_,
                                                nullptr, nullptr, p_res, nullptr, 0, nullptr);

    // 3. in_ln -> packed
    rmsnorm_kernel<<<T_, 256>>>(p_x, in_ln_w, nullptr, p_xnp);

    // 4. fused qkv: q,k fp32 -> g_qkv ; v packed -> g_vp
    gemm_b16_qkv<<<dim3(24, T_ / 128), 256>>>(p_xnp, wq, wk, wv);

    // 5. q/k norm + rope -> packed planes
    qkrope_kernel<<<dim3(T_, NH_), DH_>>>(0, p_qp, NH_ * DH_, q_norm_w, positions);
    qkrope_kernel<<<dim3(T_, NKV_), DH_>>>(2048, p_kp, NKV_ * DH_, k_norm_w, positions);

    // 6. attention: QK^T -> softmax(pack) -> PV
    gemm_b16_qk<<<dim3(T_ / 128, T_ / 128, NH_), 256>>>();
    softmax_rows<<<dim3(T_, NH_), 256>>>();
    gemm_b16_pv<<<dim3(T_ / 128, NH_), 256>>>();

    // 7. wo + residual -> x
    gemm_b16<<<dim3(H_ / 128, T_ / 128), 256>>>(p_attnp, wo, p_x,
                                                T_, NH_ * DH_, NH_ * DH_, H_, H_,
                                                nullptr, p_res, nullptr, nullptr, 0, nullptr);

    // 8. post_ln -> fp32 (router) + packed (MoE)
    rmsnorm_kernel<<<T_, 256>>>(p_x, post_ln_w, p_xn, p_xnp);

    // 9. router + bucketing
    zero_counts_kernel<<<1, 32>>>();
    router_kernel<<<T_, 256>>>(router_w);
    offsets_kernel<<<1, 32>>>();
    scatter_kernel<<<(T_ + 255) / 256, 256>>>();

    // 10. MoE grouped GEMMs
    gemm_b16<<<dim3(I_ / 128, T_ / 128, E_), 256>>>(p_xnp, w_gate, p_g,
                                                    0, H_, H_, I_, I_,
                                                    p_tok, nullptr, nullptr, p_offs,
                                                    (long long)H_ * I_, nullptr);
    gemm_b16<<<dim3(I_ / 128, T_ / 128, E_), 256>>>(p_xnp, w_up, p_u,
                                                    0, H_, H_, I_, I_,
                                                    p_tok, nullptr, nullptr, p_offs,
                                                    (long long)H_ * I_, nullptr);
    silu_mul_kernel<<<((size_t)T_ * TOPK_ * I_ + 255) / 256, 256>>>();
    gemm_b16<<<dim3(H_ / 128, T_ / 128, E_), 256>>>(p_actp, w_down, p_down,
                                                    0, I_, I_, H_, H_,
                                                    nullptr, nullptr, nullptr, p_offs,
                                                    (long long)I_ * H_, p_gate);

    // 11. combine + final rms
    final_kernel<<<T_, 256>>>(final_norm_w, out);
}